// round 7
// baseline (speedup 1.0000x reference)
#include <cuda_runtime.h>
#include <cuda_bf16.h>
#include <cstdint>
#include <math.h>

#define EMBED    1024
#define HEADS    16
#define HEAD_DIM 64
#define BATCH    2
#define SEQ      2048
#define TOKENS   (BATCH * SEQ)

// ---------------------------------------------------------------------------
// Scratch (device globals)
// ---------------------------------------------------------------------------
__device__ __nv_bfloat16 g_in_hi[3 * TOKENS * EMBED];
__device__ __nv_bfloat16 g_in_lo[3 * TOKENS * EMBED];
__device__ __nv_bfloat16 g_w_hi [4 * EMBED * EMBED];
__device__ __nv_bfloat16 g_w_lo [4 * EMBED * EMBED];
__device__ __nv_bfloat16 g_qh[TOKENS * EMBED], g_ql[TOKENS * EMBED];
__device__ __nv_bfloat16 g_kh[TOKENS * EMBED], g_kl[TOKENS * EMBED];
__device__ __nv_bfloat16 g_vh[TOKENS * EMBED], g_vl[TOKENS * EMBED];
__device__ __nv_bfloat16 g_ao_hi[TOKENS * EMBED];
__device__ __nv_bfloat16 g_ao_lo[TOKENS * EMBED];

__device__ __forceinline__ uint32_t smem_u32(const void* p) {
    uint32_t a;
    asm("{ .reg .u64 t; cvta.to.shared.u64 t, %1; cvt.u32.u64 %0, t; }"
        : "=r"(a) : "l"(p));
    return a;
}
__device__ __forceinline__ float fast_exp2(float x) {
    float y;
    asm("ex2.approx.f32 %0, %1;" : "=f"(y) : "f"(x));
    return y;
}
__device__ __forceinline__ uint32_t split2(float a, float b, uint32_t& lo) {
    __nv_bfloat162 h = __floats2bfloat162_rn(a, b);
    __nv_bfloat162 l = __floats2bfloat162_rn(
        a - __bfloat162float(__low2bfloat16(h)),
        b - __bfloat162float(__high2bfloat16(h)));
    lo = *reinterpret_cast<uint32_t*>(&l);
    return *reinterpret_cast<uint32_t*>(&h);
}

#define LDSM4(r, a) \
    asm volatile("ldmatrix.sync.aligned.m8n8.x4.shared.b16 {%0,%1,%2,%3}, [%4];" \
                 : "=r"((r)[0]), "=r"((r)[1]), "=r"((r)[2]), "=r"((r)[3]) : "r"(a))
#define LDSM4T(r, a) \
    asm volatile("ldmatrix.sync.aligned.m8n8.x4.trans.shared.b16 {%0,%1,%2,%3}, [%4];" \
                 : "=r"((r)[0]), "=r"((r)[1]), "=r"((r)[2]), "=r"((r)[3]) : "r"(a))
#define MMA16816(d, a, b) \
    asm volatile("mma.sync.aligned.m16n8k16.row.col.f32.bf16.bf16.f32 " \
                 "{%0,%1,%2,%3}, {%4,%5,%6,%7}, {%8,%9}, {%0,%1,%2,%3};" \
                 : "+f"((d)[0]), "+f"((d)[1]), "+f"((d)[2]), "+f"((d)[3]) \
                 : "r"((a)[0]), "r"((a)[1]), "r"((a)[2]), "r"((a)[3]), \
                   "r"((b)[0]), "r"((b)[1]))
#define CP16(dst, src) \
    asm volatile("cp.async.ca.shared.global [%0], [%1], 16;" \
                 :: "r"(dst), "l"(src) : "memory")
#define CP_COMMIT() asm volatile("cp.async.commit_group;" ::: "memory")
#define CP_WAIT(n)  asm volatile("cp.async.wait_group %0;" :: "n"(n) : "memory")

// ---------------------------------------------------------------------------
// Fused fp32 -> bf16 hi/lo split (one launch for 3 inputs + 4 weights)
// ---------------------------------------------------------------------------
__global__ __launch_bounds__(256)
void cvt_split_all_kernel(const float4* __restrict__ q, const float4* __restrict__ k,
                          const float4* __restrict__ v,
                          const float4* __restrict__ wq, const float4* __restrict__ wk,
                          const float4* __restrict__ wv, const float4* __restrict__ wo,
                          uint2* __restrict__ ih, uint2* __restrict__ il,
                          uint2* __restrict__ wh, uint2* __restrict__ wl)
{
    const int NI = TOKENS * EMBED / 4;
    const int NW = EMBED * EMBED / 4;
    int i = blockIdx.x * 256 + threadIdx.x;

    const float4* src;
    uint2 *H, *L;
    if (i < 3 * NI) {
        int seg = i / NI;
        int off = i - seg * NI;
        src = (seg == 0 ? q : seg == 1 ? k : v) + off;
        H = ih + (size_t)seg * NI + off;
        L = il + (size_t)seg * NI + off;
    } else {
        int j = i - 3 * NI;
        int seg = j / NW;
        int off = j - seg * NW;
        src = (seg == 0 ? wq : seg == 1 ? wk : seg == 2 ? wv : wo) + off;
        H = wh + (size_t)seg * NW + off;
        L = wl + (size_t)seg * NW + off;
    }
    float4 val = *src;
    uint2 Hv, Lv;
    Hv.x = split2(val.x, val.y, Lv.x);
    Hv.y = split2(val.z, val.w, Lv.y);
    *H = Hv;
    *L = Lv;
}

// ---------------------------------------------------------------------------
// bf16x3 tensor-core GEMM: CTA tile 128m x 256n, BK=32, 8 warps of 64x64.
// MMA/LDSM4 ratio 6 -> smem crossbar no longer binds; 3-stage cp.async.
// smem/stage: Ahi 8K | Alo 8K | Bhi 16K | Blo 16K = 48KB; 3 stages = 144KB.
// ---------------------------------------------------------------------------
__device__ __forceinline__ uint32_t swz(int m, int c) {
    return (uint32_t)((m >> 1) * 128 + (((((m & 1) << 2) | c) ^ ((m >> 1) & 7)) << 4));
}

#define G_STAGE 49152
#define GEMM_SMEM (3 * G_STAGE)
#define oAh 0u
#define oAl 8192u
#define oBh 16384u
#define oBl 32768u

__global__ __launch_bounds__(256)
void gemm_bf16x3_kernel(const __nv_bfloat16* __restrict__ Ahi_b,
                        const __nv_bfloat16* __restrict__ Alo_b,
                        int strideAz,
                        const __nv_bfloat16* __restrict__ Whi_b,
                        const __nv_bfloat16* __restrict__ Wlo_b,
                        int strideWz,
                        const float* __restrict__ b0, const float* __restrict__ b1,
                        const float* __restrict__ b2,
                        float* __restrict__ Cf,
                        __nv_bfloat16* __restrict__ H0, __nv_bfloat16* __restrict__ H1,
                        __nv_bfloat16* __restrict__ H2,
                        __nv_bfloat16* __restrict__ L0, __nv_bfloat16* __restrict__ L1,
                        __nv_bfloat16* __restrict__ L2)
{
    extern __shared__ char sm[];
    const uint32_t sb = smem_u32(sm);
    const int tid  = threadIdx.x;
    const int wid  = tid >> 5;
    const int lane = tid & 31;

    const int z = blockIdx.z;
    const __nv_bfloat16* Ahi = Ahi_b + (size_t)z * strideAz;
    const __nv_bfloat16* Alo = Alo_b + (size_t)z * strideAz;
    const __nv_bfloat16* Whi = Whi_b + (size_t)z * strideWz;
    const __nv_bfloat16* Wlo = Wlo_b + (size_t)z * strideWz;
    const float* bias = (z == 0) ? b0 : (z == 1) ? b1 : b2;

    const int row0 = blockIdx.y * 128;
    const int col0 = blockIdx.x * 256;
    const int wm = (wid & 1) * 64;      // warp m offset (2 m-warps)
    const int wn = (wid >> 1) * 64;     // warp n offset (4 n-warps x 64 = 256)

    // loaders: A = 128 rows x 4 units (2 per thread, 2 planes); B = 256 rows x 4 units
    const int lmA = tid >> 1;
    const int lcA = (tid & 1) * 2;
    const __nv_bfloat16* gAh = Ahi + (size_t)(row0 + lmA) * EMBED + lcA * 8;
    const __nv_bfloat16* gAl = Alo + (size_t)(row0 + lmA) * EMBED + lcA * 8;
    const __nv_bfloat16* gWh = Whi + (size_t)(col0 + tid) * EMBED;
    const __nv_bfloat16* gWl = Wlo + (size_t)(col0 + tid) * EMBED;
    const uint32_t sA0 = swz(lmA, lcA);
    const uint32_t sA1 = swz(lmA, lcA + 1);
    const uint32_t sB0 = swz(tid, 0), sB1 = swz(tid, 1),
                   sB2 = swz(tid, 2), sB3 = swz(tid, 3);

    float acc[4][8][4];
#pragma unroll
    for (int i = 0; i < 4; i++)
#pragma unroll
        for (int j = 0; j < 8; j++)
#pragma unroll
            for (int q = 0; q < 4; q++) acc[i][j][q] = 0.0f;

    auto issue = [&](int ch) {
        const uint32_t st = sb + (uint32_t)(ch % 3) * G_STAGE;
        const int ko = ch * 32;
        CP16(st + oAh + sA0, gAh + ko);
        CP16(st + oAh + sA1, gAh + ko + 8);
        CP16(st + oAl + sA0, gAl + ko);
        CP16(st + oAl + sA1, gAl + ko + 8);
        CP16(st + oBh + sB0, gWh + ko);
        CP16(st + oBh + sB1, gWh + ko + 8);
        CP16(st + oBh + sB2, gWh + ko + 16);
        CP16(st + oBh + sB3, gWh + ko + 24);
        CP16(st + oBl + sB0, gWl + ko);
        CP16(st + oBl + sB1, gWl + ko + 8);
        CP16(st + oBl + sB2, gWl + ko + 16);
        CP16(st + oBl + sB3, gWl + ko + 24);
    };

    issue(0); CP_COMMIT();
    issue(1); CP_COMMIT();

    const int mA  = wm + (lane & 7) + ((lane >> 3) & 1) * 8;
    const int cA  = (lane >> 4);
    const int nB4 = wn + (lane & 7) + ((lane >> 4) << 3);
    const int cB4 = ((lane >> 3) & 1);

    const int NCHUNK = EMBED / 32;
    for (int ch = 0; ch < NCHUNK; ch++) {
        if (ch + 1 < NCHUNK) { CP_WAIT(1); } else { CP_WAIT(0); }
        __syncthreads();
        if (ch + 2 < NCHUNK) { issue(ch + 2); CP_COMMIT(); }

        const uint32_t stb = sb + (uint32_t)(ch % 3) * G_STAGE;
#pragma unroll
        for (int ks = 0; ks < 2; ks++) {
            uint32_t ah[4][4], al[4][4], bh[8][2], bl[8][2];
            const int ca = ks * 2 + cA;
            const int cb = ks * 2 + cB4;
#pragma unroll
            for (int i = 0; i < 4; i++) {
                LDSM4(ah[i], stb + oAh + swz(mA + i * 16, ca));
                LDSM4(al[i], stb + oAl + swz(mA + i * 16, ca));
            }
#pragma unroll
            for (int jj = 0; jj < 4; jj++) {
                uint32_t t[4];
                LDSM4(t, stb + oBh + swz(nB4 + jj * 16, cb));
                bh[2 * jj][0] = t[0]; bh[2 * jj][1] = t[1];
                bh[2 * jj + 1][0] = t[2]; bh[2 * jj + 1][1] = t[3];
                LDSM4(t, stb + oBl + swz(nB4 + jj * 16, cb));
                bl[2 * jj][0] = t[0]; bl[2 * jj][1] = t[1];
                bl[2 * jj + 1][0] = t[2]; bl[2 * jj + 1][1] = t[3];
            }
#pragma unroll
            for (int i = 0; i < 4; i++)
#pragma unroll
                for (int j = 0; j < 8; j++) {
                    MMA16816(acc[i][j], ah[i], bh[j]);
                    MMA16816(acc[i][j], al[i], bh[j]);
                    MMA16816(acc[i][j], ah[i], bl[j]);
                }
        }
    }

    const int mrow = row0 + wm + (lane >> 2);
    const int ncol = col0 + wn + (lane & 3) * 2;
    if (H0) {
        __nv_bfloat16* Hi = (z == 0) ? H0 : (z == 1) ? H1 : H2;
        __nv_bfloat16* Lo = (z == 0) ? L0 : (z == 1) ? L1 : L2;
#pragma unroll
        for (int i = 0; i < 4; i++)
#pragma unroll
            for (int j = 0; j < 8; j++) {
                const int r  = mrow + i * 16;
                const int cn = ncol + j * 8;
                const float bx = bias[cn], by = bias[cn + 1];
                uint32_t l0v, l1v;
                uint32_t h0v = split2(acc[i][j][0] + bx, acc[i][j][1] + by, l0v);
                uint32_t h1v = split2(acc[i][j][2] + bx, acc[i][j][3] + by, l1v);
                *(uint32_t*)(Hi + (size_t)r       * EMBED + cn) = h0v;
                *(uint32_t*)(Lo + (size_t)r       * EMBED + cn) = l0v;
                *(uint32_t*)(Hi + (size_t)(r + 8) * EMBED + cn) = h1v;
                *(uint32_t*)(Lo + (size_t)(r + 8) * EMBED + cn) = l1v;
            }
    } else {
#pragma unroll
        for (int i = 0; i < 4; i++)
#pragma unroll
            for (int j = 0; j < 8; j++) {
                const int r  = mrow + i * 16;
                const int cn = ncol + j * 8;
                const float bx = bias[cn], by = bias[cn + 1];
                float2 v0 = make_float2(acc[i][j][0] + bx, acc[i][j][1] + by);
                float2 v1 = make_float2(acc[i][j][2] + bx, acc[i][j][3] + by);
                *(float2*)(Cf + (size_t)r       * EMBED + cn) = v0;
                *(float2*)(Cf + (size_t)(r + 8) * EMBED + cn) = v1;
            }
    }
}

// ---------------------------------------------------------------------------
// Tensor-core flash attention (bf16x3). K-tile = 64, 2-stage cp.async.
// (unchanged from Round 6)
// ---------------------------------------------------------------------------
#define KT 64
#define ATT_STAGE (4 * 8192 + 256)
#define ATT_SMEM  (2 * 16384 + 2 * ATT_STAGE)

__global__ __launch_bounds__(256, 2)
void attention_tc_kernel(const __nv_bfloat16* __restrict__ Qh,
                         const __nv_bfloat16* __restrict__ Ql,
                         const __nv_bfloat16* __restrict__ Kh,
                         const __nv_bfloat16* __restrict__ Kl,
                         const __nv_bfloat16* __restrict__ Vh,
                         const __nv_bfloat16* __restrict__ Vl,
                         const int* __restrict__ mask,
                         __nv_bfloat16* __restrict__ Ohi,
                         __nv_bfloat16* __restrict__ Olo)
{
    extern __shared__ char sm[];
    const uint32_t sb = smem_u32(sm);
    const uint32_t oQh = 0, oQl = 16384, oStage = 32768;
    const int tid  = threadIdx.x;
    const int lane = tid & 31;
    const int w    = tid >> 5;
    const int qt   = blockIdx.x;
    const int h    = blockIdx.y;
    const int b    = blockIdx.z;
    const int colh = h * HEAD_DIM;
    const size_t base = (size_t)b * SEQ * EMBED;
    const float CEXP = 1.4426950408889634f / 32.0f;

    auto issueKV = [&](int kt) {
        const uint32_t ksb = sb + oStage + (uint32_t)(kt & 1) * ATT_STAGE;
#pragma unroll
        for (int it = 0; it < 2; it++) {
            int idx = tid + it * 256;
            int r = idx >> 3, u = idx & 7;
            size_t g = base + (size_t)(kt * KT + r) * EMBED + colh + u * 8;
            uint32_t so = (uint32_t)(r * 128 + ((u ^ (r & 7)) << 4));
            CP16(ksb             + so, Kh + g);
            CP16(ksb +     8192u + so, Kl + g);
            CP16(ksb + 2 * 8192u + so, Vh + g);
            CP16(ksb + 3 * 8192u + so, Vl + g);
        }
        if (tid < 16)
            CP16(ksb + 4 * 8192u + (uint32_t)tid * 16u,
                 mask + b * SEQ + kt * KT + tid * 4);
    };

    issueKV(0); CP_COMMIT();

#pragma unroll
    for (int it = 0; it < 4; it++) {
        int idx = tid + it * 256;
        int r = idx >> 3, u = idx & 7;
        size_t g = base + (size_t)(qt * 128 + r) * EMBED + colh + u * 8;
        uint32_t so = (uint32_t)(r * 128 + ((u ^ (r & 7)) << 4));
        *(uint4*)(sm + oQh + so) = *(const uint4*)(Qh + g);
        *(uint4*)(sm + oQl + so) = *(const uint4*)(Ql + g);
    }

    const int q0 = w * 16;
    float o[8][4];
#pragma unroll
    for (int j = 0; j < 8; j++)
#pragma unroll
        for (int q = 0; q < 4; q++) o[j][q] = 0.0f;
    const float NEG_INF = __int_as_float(0xff800000);
    float mr0 = NEG_INF, mr1 = NEG_INF, lr0 = 0.0f, lr1 = 0.0f;

    const uint32_t rowA = (uint32_t)(q0 + (lane & 15));
    const uint32_t uA   = (uint32_t)(lane >> 4);
    const uint32_t rowB = (uint32_t)((lane & 7) + ((lane >> 4) << 3));
    const uint32_t uB   = (uint32_t)((lane >> 3) & 1);
    const uint32_t rowV = (uint32_t)((lane & 7) + (((lane >> 3) & 1) << 3));
    const uint32_t uV   = (uint32_t)(lane >> 4);

    const int NITER = SEQ / KT;
    for (int kt = 0; kt < NITER; kt++) {
        if (kt + 1 < NITER) { issueKV(kt + 1); CP_COMMIT(); CP_WAIT(1); }
        else                { CP_WAIT(0); }
        __syncthreads();

        const uint32_t stg = sb + oStage + (uint32_t)(kt & 1) * ATT_STAGE;
        const uint32_t oKh = stg, oKl = stg + 8192, oVh = stg + 2 * 8192,
                       oVl = stg + 3 * 8192;
        const int* msk = (const int*)(sm + (oStage + (uint32_t)(kt & 1) * ATT_STAGE
                                            + 4 * 8192));

        float s[8][4];
#pragma unroll
        for (int j = 0; j < 8; j++)
#pragma unroll
            for (int q = 0; q < 4; q++) s[j][q] = 0.0f;

#pragma unroll
        for (int ks = 0; ks < 4; ks++) {
            uint32_t ah[4], al[4];
            const uint32_t ua = uA + ks * 2;
            const uint32_t aoff = rowA * 128 + ((ua ^ (rowA & 7)) << 4);
            LDSM4(ah, sb + oQh + aoff);
            LDSM4(al, sb + oQl + aoff);
#pragma unroll
            for (int np = 0; np < 4; np++) {
                const uint32_t rb = rowB + np * 16;
                const uint32_t ub = uB + ks * 2;
                const uint32_t boff = rb * 128 + ((ub ^ (rb & 7)) << 4);
                uint32_t kh4[4], kl4[4];
                LDSM4(kh4, oKh + boff);
                LDSM4(kl4, oKl + boff);
                MMA16816(s[2 * np],     ah, kh4);
                MMA16816(s[2 * np],     al, kh4);
                MMA16816(s[2 * np],     ah, kl4);
                MMA16816(s[2 * np + 1], ah, kh4 + 2);
                MMA16816(s[2 * np + 1], al, kh4 + 2);
                MMA16816(s[2 * np + 1], ah, kl4 + 2);
            }
        }

        const int cb2 = (lane & 3) * 2;
        float mx0 = NEG_INF, mx1 = NEG_INF;
#pragma unroll
        for (int j = 0; j < 8; j++) {
            const int col = j * 8 + cb2;
            const int m0v = msk[col], m1v = msk[col + 1];
            if (!m0v) { s[j][0] = -1e20f; s[j][2] = -1e20f; }
            if (!m1v) { s[j][1] = -1e20f; s[j][3] = -1e20f; }
            mx0 = fmaxf(mx0, fmaxf(s[j][0], s[j][1]));
            mx1 = fmaxf(mx1, fmaxf(s[j][2], s[j][3]));
        }
        mx0 = fmaxf(mx0, __shfl_xor_sync(0xffffffffu, mx0, 1));
        mx0 = fmaxf(mx0, __shfl_xor_sync(0xffffffffu, mx0, 2));
        mx1 = fmaxf(mx1, __shfl_xor_sync(0xffffffffu, mx1, 1));
        mx1 = fmaxf(mx1, __shfl_xor_sync(0xffffffffu, mx1, 2));

        const float mn0 = fmaxf(mr0, mx0);
        const float mn1 = fmaxf(mr1, mx1);
        const float c0 = fast_exp2((mr0 - mn0) * CEXP);
        const float c1 = fast_exp2((mr1 - mn1) * CEXP);
        mr0 = mn0; mr1 = mn1;

        float sum0 = 0.0f, sum1 = 0.0f;
#pragma unroll
        for (int j = 0; j < 8; j++) {
            s[j][0] = fast_exp2((s[j][0] - mn0) * CEXP);
            s[j][1] = fast_exp2((s[j][1] - mn0) * CEXP);
            s[j][2] = fast_exp2((s[j][2] - mn1) * CEXP);
            s[j][3] = fast_exp2((s[j][3] - mn1) * CEXP);
            sum0 += s[j][0] + s[j][1];
            sum1 += s[j][2] + s[j][3];
        }
        sum0 += __shfl_xor_sync(0xffffffffu, sum0, 1);
        sum0 += __shfl_xor_sync(0xffffffffu, sum0, 2);
        sum1 += __shfl_xor_sync(0xffffffffu, sum1, 1);
        sum1 += __shfl_xor_sync(0xffffffffu, sum1, 2);
        lr0 = lr0 * c0 + sum0;
        lr1 = lr1 * c1 + sum1;
#pragma unroll
        for (int jd = 0; jd < 8; jd++) {
            o[jd][0] *= c0; o[jd][1] *= c0;
            o[jd][2] *= c1; o[jd][3] *= c1;
        }

#pragma unroll
        for (int kk = 0; kk < 4; kk++) {
            uint32_t ph[4], pl[4];
            ph[0] = split2(s[2 * kk][0],     s[2 * kk][1],     pl[0]);
            ph[1] = split2(s[2 * kk][2],     s[2 * kk][3],     pl[1]);
            ph[2] = split2(s[2 * kk + 1][0], s[2 * kk + 1][1], pl[2]);
            ph[3] = split2(s[2 * kk + 1][2], s[2 * kk + 1][3], pl[3]);
            const uint32_t k0 = kk * 16;
#pragma unroll
            for (int jdp = 0; jdp < 4; jdp++) {
                const uint32_t rv = k0 + rowV;
                const uint32_t uv = jdp * 2 + uV;
                const uint32_t voff = rv * 128 + ((uv ^ (rv & 7)) << 4);
                uint32_t bh4[4], bl4[4];
                LDSM4T(bh4, oVh + voff);
                LDSM4T(bl4, oVl + voff);
                MMA16816(o[2 * jdp],     ph, bh4);
                MMA16816(o[2 * jdp],     pl, bh4);
                MMA16816(o[2 * jdp],     ph, bl4);
                MMA16816(o[2 * jdp + 1], ph, bh4 + 2);
                MMA16816(o[2 * jdp + 1], pl, bh4 + 2);
                MMA16816(o[2 * jdp + 1], ph, bl4 + 2);
            }
        }
        __syncthreads();
    }

    const float inv0 = 1.0f / lr0;
    const float inv1 = 1.0f / lr1;
    const int r0g = qt * 128 + q0 + (lane >> 2);
    const int cbe = (lane & 3) * 2;
#pragma unroll
    for (int jd = 0; jd < 8; jd++) {
        const int cn = colh + jd * 8 + cbe;
        uint32_t l0v, l1v;
        uint32_t h0v = split2(o[jd][0] * inv0, o[jd][1] * inv0, l0v);
        uint32_t h1v = split2(o[jd][2] * inv1, o[jd][3] * inv1, l1v);
        size_t i0 = base + (size_t)r0g * EMBED + cn;
        size_t i1 = base + (size_t)(r0g + 8) * EMBED + cn;
        *(uint32_t*)(Ohi + i0) = h0v;
        *(uint32_t*)(Olo + i0) = l0v;
        *(uint32_t*)(Ohi + i1) = h1v;
        *(uint32_t*)(Olo + i1) = l1v;
    }
}

// ---------------------------------------------------------------------------
// Launch
// ---------------------------------------------------------------------------
extern "C" void kernel_launch(void* const* d_in, const int* in_sizes, int n_in,
                              void* d_out, int out_size)
{
    const float* query = (const float*)d_in[0];
    const float* key   = (const float*)d_in[1];
    const float* value = (const float*)d_in[2];
    const int*   mask  = (const int*)  d_in[3];
    const float* Wq    = (const float*)d_in[4];
    const float* bq    = (const float*)d_in[5];
    const float* Wk    = (const float*)d_in[6];
    const float* bk    = (const float*)d_in[7];
    const float* Wv    = (const float*)d_in[8];
    const float* bv    = (const float*)d_in[9];
    const float* Wo    = (const float*)d_in[10];
    const float* bo    = (const float*)d_in[11];
    float* out = (float*)d_out;

    __nv_bfloat16 *ih, *il, *wh, *wl, *aoh, *aol;
    __nv_bfloat16 *qh, *ql, *kh, *kl, *vh, *vl;
    cudaGetSymbolAddress((void**)&ih,  g_in_hi);
    cudaGetSymbolAddress((void**)&il,  g_in_lo);
    cudaGetSymbolAddress((void**)&wh,  g_w_hi);
    cudaGetSymbolAddress((void**)&wl,  g_w_lo);
    cudaGetSymbolAddress((void**)&aoh, g_ao_hi);
    cudaGetSymbolAddress((void**)&aol, g_ao_lo);
    cudaGetSymbolAddress((void**)&qh,  g_qh);
    cudaGetSymbolAddress((void**)&ql,  g_ql);
    cudaGetSymbolAddress((void**)&kh,  g_kh);
    cudaGetSymbolAddress((void**)&kl,  g_kl);
    cudaGetSymbolAddress((void**)&vh,  g_vh);
    cudaGetSymbolAddress((void**)&vl,  g_vl);

    cudaFuncSetAttribute(gemm_bf16x3_kernel,
                         cudaFuncAttributeMaxDynamicSharedMemorySize, GEMM_SMEM);
    cudaFuncSetAttribute(attention_tc_kernel,
                         cudaFuncAttributeMaxDynamicSharedMemorySize, ATT_SMEM);

    // One fused split pass
    const int NI = TOKENS * EMBED / 4;
    const int NW = EMBED * EMBED / 4;
    cvt_split_all_kernel<<<(3 * NI + 4 * NW) / 256, 256>>>(
        (const float4*)query, (const float4*)key, (const float4*)value,
        (const float4*)Wq, (const float4*)Wk, (const float4*)Wv, (const float4*)Wo,
        (uint2*)ih, (uint2*)il, (uint2*)wh, (uint2*)wl);

    // QKV projections -> bf16 hi/lo planes (CTA tile 128x256)
    gemm_bf16x3_kernel<<<dim3(EMBED / 256, TOKENS / 128, 3), 256, GEMM_SMEM>>>(
        ih, il, TOKENS * EMBED, wh, wl, EMBED * EMBED,
        bq, bk, bv, nullptr, qh, kh, vh, ql, kl, vl);

    // Tensor-core flash attention
    attention_tc_kernel<<<dim3(SEQ / 128, HEADS, BATCH), 256, ATT_SMEM>>>(
        qh, ql, kh, kl, vh, vl, mask, aoh, aol);

    // Output projection -> fp32
    gemm_bf16x3_kernel<<<dim3(EMBED / 256, TOKENS / 128, 1), 256, GEMM_SMEM>>>(
        aoh, aol, 0, wh + (size_t)3 * EMBED * EMBED, wl + (size_t)3 * EMBED * EMBED, 0,
        bo, bo, bo, out,
        nullptr, nullptr, nullptr, nullptr, nullptr, nullptr);
}

// round 8
// speedup vs baseline: 1.4576x; 1.4576x over previous
#include <cuda_runtime.h>
#include <cuda_bf16.h>
#include <cstdint>
#include <math.h>

#define EMBED    1024
#define HEADS    16
#define HEAD_DIM 64
#define BATCH    2
#define SEQ      2048
#define TOKENS   (BATCH * SEQ)

// ---------------------------------------------------------------------------
// Scratch (device globals)
// ---------------------------------------------------------------------------
__device__ __nv_bfloat16 g_in_hi[3 * TOKENS * EMBED];
__device__ __nv_bfloat16 g_in_lo[3 * TOKENS * EMBED];
__device__ __nv_bfloat16 g_w_hi [4 * EMBED * EMBED];
__device__ __nv_bfloat16 g_w_lo [4 * EMBED * EMBED];
__device__ __nv_bfloat16 g_qh[TOKENS * EMBED], g_ql[TOKENS * EMBED];
__device__ __nv_bfloat16 g_kh[TOKENS * EMBED], g_kl[TOKENS * EMBED];
__device__ __nv_bfloat16 g_vh[TOKENS * EMBED], g_vl[TOKENS * EMBED];
__device__ __nv_bfloat16 g_ao_hi[TOKENS * EMBED];
__device__ __nv_bfloat16 g_ao_lo[TOKENS * EMBED];

__device__ __forceinline__ uint32_t smem_u32(const void* p) {
    uint32_t a;
    asm("{ .reg .u64 t; cvta.to.shared.u64 t, %1; cvt.u32.u64 %0, t; }"
        : "=r"(a) : "l"(p));
    return a;
}
__device__ __forceinline__ float fast_exp2(float x) {
    float y;
    asm("ex2.approx.f32 %0, %1;" : "=f"(y) : "f"(x));
    return y;
}
__device__ __forceinline__ uint32_t split2(float a, float b, uint32_t& lo) {
    __nv_bfloat162 h = __floats2bfloat162_rn(a, b);
    __nv_bfloat162 l = __floats2bfloat162_rn(
        a - __bfloat162float(__low2bfloat16(h)),
        b - __bfloat162float(__high2bfloat16(h)));
    lo = *reinterpret_cast<uint32_t*>(&l);
    return *reinterpret_cast<uint32_t*>(&h);
}

#define LDSM4(r, a) \
    asm volatile("ldmatrix.sync.aligned.m8n8.x4.shared.b16 {%0,%1,%2,%3}, [%4];" \
                 : "=r"((r)[0]), "=r"((r)[1]), "=r"((r)[2]), "=r"((r)[3]) : "r"(a))
#define LDSM4T(r, a) \
    asm volatile("ldmatrix.sync.aligned.m8n8.x4.trans.shared.b16 {%0,%1,%2,%3}, [%4];" \
                 : "=r"((r)[0]), "=r"((r)[1]), "=r"((r)[2]), "=r"((r)[3]) : "r"(a))
#define MMA16816(d, a, b) \
    asm volatile("mma.sync.aligned.m16n8k16.row.col.f32.bf16.bf16.f32 " \
                 "{%0,%1,%2,%3}, {%4,%5,%6,%7}, {%8,%9}, {%0,%1,%2,%3};" \
                 : "+f"((d)[0]), "+f"((d)[1]), "+f"((d)[2]), "+f"((d)[3]) \
                 : "r"((a)[0]), "r"((a)[1]), "r"((a)[2]), "r"((a)[3]), \
                   "r"((b)[0]), "r"((b)[1]))
#define CP16(dst, src) \
    asm volatile("cp.async.ca.shared.global [%0], [%1], 16;" \
                 :: "r"(dst), "l"(src) : "memory")
#define CP_COMMIT() asm volatile("cp.async.commit_group;" ::: "memory")
#define CP_WAIT(n)  asm volatile("cp.async.wait_group %0;" :: "n"(n) : "memory")

// 128B-row swizzle: row m, 16B unit u (0..7)
__device__ __forceinline__ uint32_t sw128(int m, int u) {
    return (uint32_t)(m * 128 + ((u ^ (m & 7)) << 4));
}

// ---------------------------------------------------------------------------
// Fused fp32 -> bf16 hi/lo split (one launch for 3 inputs + 4 weights)
// ---------------------------------------------------------------------------
__global__ __launch_bounds__(256)
void cvt_split_all_kernel(const float4* __restrict__ q, const float4* __restrict__ k,
                          const float4* __restrict__ v,
                          const float4* __restrict__ wq, const float4* __restrict__ wk,
                          const float4* __restrict__ wv, const float4* __restrict__ wo,
                          uint2* __restrict__ ih, uint2* __restrict__ il,
                          uint2* __restrict__ wh, uint2* __restrict__ wl)
{
    const int NI = TOKENS * EMBED / 4;
    const int NW = EMBED * EMBED / 4;
    int i = blockIdx.x * 256 + threadIdx.x;

    const float4* src;
    uint2 *H, *L;
    if (i < 3 * NI) {
        int seg = i / NI;
        int off = i - seg * NI;
        src = (seg == 0 ? q : seg == 1 ? k : v) + off;
        H = ih + (size_t)seg * NI + off;
        L = il + (size_t)seg * NI + off;
    } else {
        int j = i - 3 * NI;
        int seg = j / NW;
        int off = j - seg * NW;
        src = (seg == 0 ? wq : seg == 1 ? wk : seg == 2 ? wv : wo) + off;
        H = wh + (size_t)seg * NW + off;
        L = wl + (size_t)seg * NW + off;
    }
    float4 val = *src;
    uint2 Hv, Lv;
    Hv.x = split2(val.x, val.y, Lv.x);
    Hv.y = split2(val.z, val.w, Lv.y);
    *H = Hv;
    *L = Lv;
}

// ---------------------------------------------------------------------------
// bf16x3 tensor-core GEMM: 128x128 CTA tile, BK=64, 8 warps (64x32),
// 3-stage cp.async (64KB/stage), ONE __syncthreads per 64-K chunk.
// smem rows: 128 bytes (64 bf16), sw128 swizzle.
// ---------------------------------------------------------------------------
#define G_STAGE 65536
#define GEMM_SMEM (3 * G_STAGE)   // 192KB, 1 CTA/SM
#define oAh 0u
#define oAl 16384u
#define oBh 32768u
#define oBl 49152u

__global__ __launch_bounds__(256)
void gemm_bf16x3_kernel(const __nv_bfloat16* __restrict__ Ahi_b,
                        const __nv_bfloat16* __restrict__ Alo_b,
                        int strideAz,
                        const __nv_bfloat16* __restrict__ Whi_b,
                        const __nv_bfloat16* __restrict__ Wlo_b,
                        int strideWz,
                        const float* __restrict__ b0, const float* __restrict__ b1,
                        const float* __restrict__ b2,
                        float* __restrict__ Cf,
                        __nv_bfloat16* __restrict__ H0, __nv_bfloat16* __restrict__ H1,
                        __nv_bfloat16* __restrict__ H2,
                        __nv_bfloat16* __restrict__ L0, __nv_bfloat16* __restrict__ L1,
                        __nv_bfloat16* __restrict__ L2)
{
    extern __shared__ char sm[];
    const uint32_t sb = smem_u32(sm);
    const int tid  = threadIdx.x;
    const int wid  = tid >> 5;
    const int lane = tid & 31;

    const int z = blockIdx.z;
    const __nv_bfloat16* Ahi = Ahi_b + (size_t)z * strideAz;
    const __nv_bfloat16* Alo = Alo_b + (size_t)z * strideAz;
    const __nv_bfloat16* Whi = Whi_b + (size_t)z * strideWz;
    const __nv_bfloat16* Wlo = Wlo_b + (size_t)z * strideWz;
    const float* bias = (z == 0) ? b0 : (z == 1) ? b1 : b2;

    const int row0 = blockIdx.y * 128;
    const int col0 = blockIdx.x * 128;
    const int wm = (wid & 1) * 64;
    const int wn = (wid >> 1) * 32;

    // loaders: each thread owns row = tid>>1, units ubase..ubase+3 (64B)
    const int lr = tid >> 1;
    const int ub = (tid & 1) * 4;
    const __nv_bfloat16* gAh = Ahi + (size_t)(row0 + lr) * EMBED + ub * 8;
    const __nv_bfloat16* gAl = Alo + (size_t)(row0 + lr) * EMBED + ub * 8;
    const __nv_bfloat16* gWh = Whi + (size_t)(col0 + lr) * EMBED + ub * 8;
    const __nv_bfloat16* gWl = Wlo + (size_t)(col0 + lr) * EMBED + ub * 8;
    uint32_t sOf[4];
#pragma unroll
    for (int j = 0; j < 4; j++) sOf[j] = sw128(lr, ub + j);

    float acc[4][4][4];
#pragma unroll
    for (int i = 0; i < 4; i++)
#pragma unroll
        for (int j = 0; j < 4; j++)
#pragma unroll
            for (int q = 0; q < 4; q++) acc[i][j][q] = 0.0f;

    auto issue = [&](int ch) {
        const uint32_t st = sb + (uint32_t)(ch % 3) * G_STAGE;
        const int ko = ch * 64;
#pragma unroll
        for (int j = 0; j < 4; j++) {
            CP16(st + oAh + sOf[j], gAh + ko + j * 8);
            CP16(st + oAl + sOf[j], gAl + ko + j * 8);
            CP16(st + oBh + sOf[j], gWh + ko + j * 8);
            CP16(st + oBl + sOf[j], gWl + ko + j * 8);
        }
    };

    issue(0); CP_COMMIT();
    issue(1); CP_COMMIT();

    const int mA  = wm + (lane & 7) + ((lane >> 3) & 1) * 8;
    const int cA  = (lane >> 4);
    const int nB4 = wn + (lane & 7) + ((lane >> 4) << 3);
    const int cB4 = ((lane >> 3) & 1);

    const int NCHUNK = EMBED / 64;   // 16
    for (int ch = 0; ch < NCHUNK; ch++) {
        if (ch + 1 < NCHUNK) { CP_WAIT(1); } else { CP_WAIT(0); }
        __syncthreads();
        if (ch + 2 < NCHUNK) { issue(ch + 2); CP_COMMIT(); }

        const uint32_t stb = sb + (uint32_t)(ch % 3) * G_STAGE;
#pragma unroll
        for (int ks = 0; ks < 4; ks++) {
            uint32_t ah[4][4], al[4][4], bh[4][2], bl[4][2];
            const int ca = ks * 2 + cA;
            const int cb = ks * 2 + cB4;
#pragma unroll
            for (int i = 0; i < 4; i++) {
                LDSM4(ah[i], stb + oAh + sw128(mA + i * 16, ca));
                LDSM4(al[i], stb + oAl + sw128(mA + i * 16, ca));
            }
#pragma unroll
            for (int jj = 0; jj < 2; jj++) {
                uint32_t t[4];
                LDSM4(t, stb + oBh + sw128(nB4 + jj * 16, cb));
                bh[2 * jj][0] = t[0]; bh[2 * jj][1] = t[1];
                bh[2 * jj + 1][0] = t[2]; bh[2 * jj + 1][1] = t[3];
                LDSM4(t, stb + oBl + sw128(nB4 + jj * 16, cb));
                bl[2 * jj][0] = t[0]; bl[2 * jj][1] = t[1];
                bl[2 * jj + 1][0] = t[2]; bl[2 * jj + 1][1] = t[3];
            }
#pragma unroll
            for (int i = 0; i < 4; i++)
#pragma unroll
                for (int j = 0; j < 4; j++) {
                    MMA16816(acc[i][j], ah[i], bh[j]);
                    MMA16816(acc[i][j], al[i], bh[j]);
                    MMA16816(acc[i][j], ah[i], bl[j]);
                }
        }
    }

    const int mrow = row0 + wm + (lane >> 2);
    const int ncol = col0 + wn + (lane & 3) * 2;
    if (H0) {
        __nv_bfloat16* Hi = (z == 0) ? H0 : (z == 1) ? H1 : H2;
        __nv_bfloat16* Lo = (z == 0) ? L0 : (z == 1) ? L1 : L2;
#pragma unroll
        for (int i = 0; i < 4; i++)
#pragma unroll
            for (int j = 0; j < 4; j++) {
                const int r  = mrow + i * 16;
                const int cn = ncol + j * 8;
                const float bx = bias[cn], by = bias[cn + 1];
                uint32_t l0v, l1v;
                uint32_t h0v = split2(acc[i][j][0] + bx, acc[i][j][1] + by, l0v);
                uint32_t h1v = split2(acc[i][j][2] + bx, acc[i][j][3] + by, l1v);
                *(uint32_t*)(Hi + (size_t)r       * EMBED + cn) = h0v;
                *(uint32_t*)(Lo + (size_t)r       * EMBED + cn) = l0v;
                *(uint32_t*)(Hi + (size_t)(r + 8) * EMBED + cn) = h1v;
                *(uint32_t*)(Lo + (size_t)(r + 8) * EMBED + cn) = l1v;
            }
    } else {
#pragma unroll
        for (int i = 0; i < 4; i++)
#pragma unroll
            for (int j = 0; j < 4; j++) {
                const int r  = mrow + i * 16;
                const int cn = ncol + j * 8;
                const float bx = bias[cn], by = bias[cn + 1];
                float2 v0 = make_float2(acc[i][j][0] + bx, acc[i][j][1] + by);
                float2 v1 = make_float2(acc[i][j][2] + bx, acc[i][j][3] + by);
                *(float2*)(Cf + (size_t)r       * EMBED + cn) = v0;
                *(float2*)(Cf + (size_t)(r + 8) * EMBED + cn) = v1;
            }
    }
}

// ---------------------------------------------------------------------------
// Tensor-core flash attention. QK^T uses 2-term (QhKh + QlKh; Kl plane
// dropped entirely), PV keeps 3 terms. K-tile 64, 2-stage cp.async.
// stage: Kh(8K) Vh(8K) Vl(8K) + mask(256B).
// ---------------------------------------------------------------------------
#define KT 64
#define ATT_STAGE (3 * 8192 + 256)
#define ATT_SMEM  (2 * 16384 + 2 * ATT_STAGE)   // 82432 B; 2 CTAs/SM

__global__ __launch_bounds__(256, 2)
void attention_tc_kernel(const __nv_bfloat16* __restrict__ Qh,
                         const __nv_bfloat16* __restrict__ Ql,
                         const __nv_bfloat16* __restrict__ Kh,
                         const __nv_bfloat16* __restrict__ Vh,
                         const __nv_bfloat16* __restrict__ Vl,
                         const int* __restrict__ mask,
                         __nv_bfloat16* __restrict__ Ohi,
                         __nv_bfloat16* __restrict__ Olo)
{
    extern __shared__ char sm[];
    const uint32_t sb = smem_u32(sm);
    const uint32_t oQh = 0, oQl = 16384, oStage = 32768;
    const int tid  = threadIdx.x;
    const int lane = tid & 31;
    const int w    = tid >> 5;
    const int qt   = blockIdx.x;
    const int h    = blockIdx.y;
    const int b    = blockIdx.z;
    const int colh = h * HEAD_DIM;
    const size_t base = (size_t)b * SEQ * EMBED;
    const float CEXP = 1.4426950408889634f / 32.0f;

    auto issueKV = [&](int kt) {
        const uint32_t ksb = sb + oStage + (uint32_t)(kt & 1) * ATT_STAGE;
#pragma unroll
        for (int it = 0; it < 2; it++) {
            int idx = tid + it * 256;
            int r = idx >> 3, u = idx & 7;
            size_t g = base + (size_t)(kt * KT + r) * EMBED + colh + u * 8;
            uint32_t so = sw128(r, u);
            CP16(ksb             + so, Kh + g);
            CP16(ksb +     8192u + so, Vh + g);
            CP16(ksb + 2 * 8192u + so, Vl + g);
        }
        if (tid < 16)
            CP16(ksb + 3 * 8192u + (uint32_t)tid * 16u,
                 mask + b * SEQ + kt * KT + tid * 4);
    };

    issueKV(0); CP_COMMIT();

#pragma unroll
    for (int it = 0; it < 4; it++) {
        int idx = tid + it * 256;
        int r = idx >> 3, u = idx & 7;
        size_t g = base + (size_t)(qt * 128 + r) * EMBED + colh + u * 8;
        uint32_t so = sw128(r, u);
        *(uint4*)(sm + oQh + so) = *(const uint4*)(Qh + g);
        *(uint4*)(sm + oQl + so) = *(const uint4*)(Ql + g);
    }

    const int q0 = w * 16;
    float o[8][4];
#pragma unroll
    for (int j = 0; j < 8; j++)
#pragma unroll
        for (int q = 0; q < 4; q++) o[j][q] = 0.0f;
    const float NEG_INF = __int_as_float(0xff800000);
    float mr0 = NEG_INF, mr1 = NEG_INF, lr0 = 0.0f, lr1 = 0.0f;

    const uint32_t rowA = (uint32_t)(q0 + (lane & 15));
    const uint32_t uA   = (uint32_t)(lane >> 4);
    const uint32_t rowB = (uint32_t)((lane & 7) + ((lane >> 4) << 3));
    const uint32_t uB   = (uint32_t)((lane >> 3) & 1);
    const uint32_t rowV = (uint32_t)((lane & 7) + (((lane >> 3) & 1) << 3));
    const uint32_t uV   = (uint32_t)(lane >> 4);

    const int NITER = SEQ / KT;
    for (int kt = 0; kt < NITER; kt++) {
        if (kt + 1 < NITER) { issueKV(kt + 1); CP_COMMIT(); CP_WAIT(1); }
        else                { CP_WAIT(0); }
        __syncthreads();

        const uint32_t stg = sb + oStage + (uint32_t)(kt & 1) * ATT_STAGE;
        const uint32_t oKh = stg, oVh = stg + 8192, oVl = stg + 2 * 8192;
        const int* msk = (const int*)(sm + (oStage + (uint32_t)(kt & 1) * ATT_STAGE
                                            + 3 * 8192));

        // ---- S = Q K^T (2-term: QhKh + QlKh) ----
        float s[8][4];
#pragma unroll
        for (int j = 0; j < 8; j++)
#pragma unroll
            for (int q = 0; q < 4; q++) s[j][q] = 0.0f;

#pragma unroll
        for (int ks = 0; ks < 4; ks++) {
            uint32_t ah[4], al[4];
            const uint32_t ua = uA + ks * 2;
            const uint32_t aoff = rowA * 128 + (((uint32_t)(ua) ^ (rowA & 7)) << 4);
            LDSM4(ah, sb + oQh + aoff);
            LDSM4(al, sb + oQl + aoff);
#pragma unroll
            for (int np = 0; np < 4; np++) {
                const uint32_t rb = rowB + np * 16;
                const uint32_t ub = uB + ks * 2;
                const uint32_t boff = rb * 128 + ((ub ^ (rb & 7)) << 4);
                uint32_t kh4[4];
                LDSM4(kh4, oKh + boff);
                MMA16816(s[2 * np],     ah, kh4);
                MMA16816(s[2 * np],     al, kh4);
                MMA16816(s[2 * np + 1], ah, kh4 + 2);
                MMA16816(s[2 * np + 1], al, kh4 + 2);
            }
        }

        // ---- mask + online softmax ----
        const int cb2 = (lane & 3) * 2;
        float mx0 = NEG_INF, mx1 = NEG_INF;
#pragma unroll
        for (int j = 0; j < 8; j++) {
            const int col = j * 8 + cb2;
            const int m0v = msk[col], m1v = msk[col + 1];
            if (!m0v) { s[j][0] = -1e20f; s[j][2] = -1e20f; }
            if (!m1v) { s[j][1] = -1e20f; s[j][3] = -1e20f; }
            mx0 = fmaxf(mx0, fmaxf(s[j][0], s[j][1]));
            mx1 = fmaxf(mx1, fmaxf(s[j][2], s[j][3]));
        }
        mx0 = fmaxf(mx0, __shfl_xor_sync(0xffffffffu, mx0, 1));
        mx0 = fmaxf(mx0, __shfl_xor_sync(0xffffffffu, mx0, 2));
        mx1 = fmaxf(mx1, __shfl_xor_sync(0xffffffffu, mx1, 1));
        mx1 = fmaxf(mx1, __shfl_xor_sync(0xffffffffu, mx1, 2));

        const float mn0 = fmaxf(mr0, mx0);
        const float mn1 = fmaxf(mr1, mx1);
        const float c0 = fast_exp2((mr0 - mn0) * CEXP);
        const float c1 = fast_exp2((mr1 - mn1) * CEXP);
        mr0 = mn0; mr1 = mn1;

        float sum0 = 0.0f, sum1 = 0.0f;
#pragma unroll
        for (int j = 0; j < 8; j++) {
            s[j][0] = fast_exp2((s[j][0] - mn0) * CEXP);
            s[j][1] = fast_exp2((s[j][1] - mn0) * CEXP);
            s[j][2] = fast_exp2((s[j][2] - mn1) * CEXP);
            s[j][3] = fast_exp2((s[j][3] - mn1) * CEXP);
            sum0 += s[j][0] + s[j][1];
            sum1 += s[j][2] + s[j][3];
        }
        sum0 += __shfl_xor_sync(0xffffffffu, sum0, 1);
        sum0 += __shfl_xor_sync(0xffffffffu, sum0, 2);
        sum1 += __shfl_xor_sync(0xffffffffu, sum1, 1);
        sum1 += __shfl_xor_sync(0xffffffffu, sum1, 2);
        lr0 = lr0 * c0 + sum0;
        lr1 = lr1 * c1 + sum1;
#pragma unroll
        for (int jd = 0; jd < 8; jd++) {
            o[jd][0] *= c0; o[jd][1] *= c0;
            o[jd][2] *= c1; o[jd][3] *= c1;
        }

        // ---- O += P V (3-term: PhVh + PlVh + PhVl) ----
#pragma unroll
        for (int kk = 0; kk < 4; kk++) {
            uint32_t ph[4], pl[4];
            ph[0] = split2(s[2 * kk][0],     s[2 * kk][1],     pl[0]);
            ph[1] = split2(s[2 * kk][2],     s[2 * kk][3],     pl[1]);
            ph[2] = split2(s[2 * kk + 1][0], s[2 * kk + 1][1], pl[2]);
            ph[3] = split2(s[2 * kk + 1][2], s[2 * kk + 1][3], pl[3]);
            const uint32_t k0 = kk * 16;
#pragma unroll
            for (int jdp = 0; jdp < 4; jdp++) {
                const uint32_t rv = k0 + rowV;
                const uint32_t uv = jdp * 2 + uV;
                const uint32_t voff = rv * 128 + ((uv ^ (rv & 7)) << 4);
                uint32_t bh4[4], bl4[4];
                LDSM4T(bh4, oVh + voff);
                LDSM4T(bl4, oVl + voff);
                MMA16816(o[2 * jdp],     ph, bh4);
                MMA16816(o[2 * jdp],     pl, bh4);
                MMA16816(o[2 * jdp],     ph, bl4);
                MMA16816(o[2 * jdp + 1], ph, bh4 + 2);
                MMA16816(o[2 * jdp + 1], pl, bh4 + 2);
                MMA16816(o[2 * jdp + 1], ph, bl4 + 2);
            }
        }
        __syncthreads();
    }

    const float inv0 = 1.0f / lr0;
    const float inv1 = 1.0f / lr1;
    const int r0g = qt * 128 + q0 + (lane >> 2);
    const int cbe = (lane & 3) * 2;
#pragma unroll
    for (int jd = 0; jd < 8; jd++) {
        const int cn = colh + jd * 8 + cbe;
        uint32_t l0v, l1v;
        uint32_t h0v = split2(o[jd][0] * inv0, o[jd][1] * inv0, l0v);
        uint32_t h1v = split2(o[jd][2] * inv1, o[jd][3] * inv1, l1v);
        size_t i0 = base + (size_t)r0g * EMBED + cn;
        size_t i1 = base + (size_t)(r0g + 8) * EMBED + cn;
        *(uint32_t*)(Ohi + i0) = h0v;
        *(uint32_t*)(Olo + i0) = l0v;
        *(uint32_t*)(Ohi + i1) = h1v;
        *(uint32_t*)(Olo + i1) = l1v;
    }
}

// ---------------------------------------------------------------------------
// Launch
// ---------------------------------------------------------------------------
extern "C" void kernel_launch(void* const* d_in, const int* in_sizes, int n_in,
                              void* d_out, int out_size)
{
    const float* query = (const float*)d_in[0];
    const float* key   = (const float*)d_in[1];
    const float* value = (const float*)d_in[2];
    const int*   mask  = (const int*)  d_in[3];
    const float* Wq    = (const float*)d_in[4];
    const float* bq    = (const float*)d_in[5];
    const float* Wk    = (const float*)d_in[6];
    const float* bk    = (const float*)d_in[7];
    const float* Wv    = (const float*)d_in[8];
    const float* bv    = (const float*)d_in[9];
    const float* Wo    = (const float*)d_in[10];
    const float* bo    = (const float*)d_in[11];
    float* out = (float*)d_out;

    __nv_bfloat16 *ih, *il, *wh, *wl, *aoh, *aol;
    __nv_bfloat16 *qh, *ql, *kh, *kl, *vh, *vl;
    cudaGetSymbolAddress((void**)&ih,  g_in_hi);
    cudaGetSymbolAddress((void**)&il,  g_in_lo);
    cudaGetSymbolAddress((void**)&wh,  g_w_hi);
    cudaGetSymbolAddress((void**)&wl,  g_w_lo);
    cudaGetSymbolAddress((void**)&aoh, g_ao_hi);
    cudaGetSymbolAddress((void**)&aol, g_ao_lo);
    cudaGetSymbolAddress((void**)&qh,  g_qh);
    cudaGetSymbolAddress((void**)&ql,  g_ql);
    cudaGetSymbolAddress((void**)&kh,  g_kh);
    cudaGetSymbolAddress((void**)&kl,  g_kl);
    cudaGetSymbolAddress((void**)&vh,  g_vh);
    cudaGetSymbolAddress((void**)&vl,  g_vl);

    cudaFuncSetAttribute(gemm_bf16x3_kernel,
                         cudaFuncAttributeMaxDynamicSharedMemorySize, GEMM_SMEM);
    cudaFuncSetAttribute(attention_tc_kernel,
                         cudaFuncAttributeMaxDynamicSharedMemorySize, ATT_SMEM);

    // One fused split pass
    const int NI = TOKENS * EMBED / 4;
    const int NW = EMBED * EMBED / 4;
    cvt_split_all_kernel<<<(3 * NI + 4 * NW) / 256, 256>>>(
        (const float4*)query, (const float4*)key, (const float4*)value,
        (const float4*)Wq, (const float4*)Wk, (const float4*)Wv, (const float4*)Wo,
        (uint2*)ih, (uint2*)il, (uint2*)wh, (uint2*)wl);

    // QKV projections -> bf16 hi/lo planes (128x128 tiles, BK=64)
    gemm_bf16x3_kernel<<<dim3(EMBED / 128, TOKENS / 128, 3), 256, GEMM_SMEM>>>(
        ih, il, TOKENS * EMBED, wh, wl, EMBED * EMBED,
        bq, bk, bv, nullptr, qh, kh, vh, ql, kl, vl);

    // Tensor-core flash attention (Kl plane unused)
    attention_tc_kernel<<<dim3(SEQ / 128, HEADS, BATCH), 256, ATT_SMEM>>>(
        qh, ql, kh, vh, vl, mask, aoh, aol);

    // Output projection -> fp32
    gemm_bf16x3_kernel<<<dim3(EMBED / 128, TOKENS / 128, 1), 256, GEMM_SMEM>>>(
        aoh, aol, 0, wh + (size_t)3 * EMBED * EMBED, wl + (size_t)3 * EMBED * EMBED, 0,
        bo, bo, bo, out,
        nullptr, nullptr, nullptr, nullptr, nullptr, nullptr);
}

// round 10
// speedup vs baseline: 1.6540x; 1.1348x over previous
#include <cuda_runtime.h>
#include <cuda_bf16.h>
#include <cstdint>
#include <math.h>

#define EMBED    1024
#define HEADS    16
#define HEAD_DIM 64
#define BATCH    2
#define SEQ      2048
#define TOKENS   (BATCH * SEQ)

// ---------------------------------------------------------------------------
// Scratch (device globals)
// ---------------------------------------------------------------------------
__device__ __nv_bfloat16 g_in_hi[3 * TOKENS * EMBED];
__device__ __nv_bfloat16 g_in_lo[3 * TOKENS * EMBED];
__device__ __nv_bfloat16 g_w_hi [4 * EMBED * EMBED];
__device__ __nv_bfloat16 g_w_lo [4 * EMBED * EMBED];
__device__ __nv_bfloat16 g_qh[TOKENS * EMBED], g_ql[TOKENS * EMBED];
__device__ __nv_bfloat16 g_kh[TOKENS * EMBED], g_kl[TOKENS * EMBED];
__device__ __nv_bfloat16 g_vh[TOKENS * EMBED], g_vl[TOKENS * EMBED];
__device__ __nv_bfloat16 g_ao_hi[TOKENS * EMBED];
__device__ __nv_bfloat16 g_ao_lo[TOKENS * EMBED];

__device__ __forceinline__ uint32_t smem_u32(const void* p) {
    uint32_t a;
    asm("{ .reg .u64 t; cvta.to.shared.u64 t, %1; cvt.u32.u64 %0, t; }"
        : "=r"(a) : "l"(p));
    return a;
}
__device__ __forceinline__ float fast_exp2(float x) {
    float y;
    asm("ex2.approx.f32 %0, %1;" : "=f"(y) : "f"(x));
    return y;
}
__device__ __forceinline__ uint32_t split2(float a, float b, uint32_t& lo) {
    __nv_bfloat162 h = __floats2bfloat162_rn(a, b);
    __nv_bfloat162 l = __floats2bfloat162_rn(
        a - __bfloat162float(__low2bfloat16(h)),
        b - __bfloat162float(__high2bfloat16(h)));
    lo = *reinterpret_cast<uint32_t*>(&l);
    return *reinterpret_cast<uint32_t*>(&h);
}

#define LDSM4(r, a) \
    asm volatile("ldmatrix.sync.aligned.m8n8.x4.shared.b16 {%0,%1,%2,%3}, [%4];" \
                 : "=r"((r)[0]), "=r"((r)[1]), "=r"((r)[2]), "=r"((r)[3]) : "r"(a))
#define LDSM4T(r, a) \
    asm volatile("ldmatrix.sync.aligned.m8n8.x4.trans.shared.b16 {%0,%1,%2,%3}, [%4];" \
                 : "=r"((r)[0]), "=r"((r)[1]), "=r"((r)[2]), "=r"((r)[3]) : "r"(a))
#define MMA16816(d, a, b) \
    asm volatile("mma.sync.aligned.m16n8k16.row.col.f32.bf16.bf16.f32 " \
                 "{%0,%1,%2,%3}, {%4,%5,%6,%7}, {%8,%9}, {%0,%1,%2,%3};" \
                 : "+f"((d)[0]), "+f"((d)[1]), "+f"((d)[2]), "+f"((d)[3]) \
                 : "r"((a)[0]), "r"((a)[1]), "r"((a)[2]), "r"((a)[3]), \
                   "r"((b)[0]), "r"((b)[1]))
#define CP16(dst, src) \
    asm volatile("cp.async.ca.shared.global [%0], [%1], 16;" \
                 :: "r"(dst), "l"(src) : "memory")
#define CP_COMMIT() asm volatile("cp.async.commit_group;" ::: "memory")
#define CP_WAIT(n)  asm volatile("cp.async.wait_group %0;" :: "n"(n) : "memory")

// GEMM smem swizzle: 2 logical 32-bf16 rows per 128B line (R6-proven)
__device__ __forceinline__ uint32_t swz(int m, int c) {
    return (uint32_t)((m >> 1) * 128 + (((((m & 1) << 2) | c) ^ ((m >> 1) & 7)) << 4));
}
// attention smem swizzle: 64-bf16 rows, 128B lines
__device__ __forceinline__ uint32_t sw128(int m, int u) {
    return (uint32_t)(m * 128 + ((u ^ (m & 7)) << 4));
}

// ---------------------------------------------------------------------------
// Fused fp32 -> bf16 hi/lo split (one launch for 3 inputs + 4 weights)
// ---------------------------------------------------------------------------
__global__ __launch_bounds__(256)
void cvt_split_all_kernel(const float4* __restrict__ q, const float4* __restrict__ k,
                          const float4* __restrict__ v,
                          const float4* __restrict__ wq, const float4* __restrict__ wk,
                          const float4* __restrict__ wv, const float4* __restrict__ wo,
                          uint2* __restrict__ ih, uint2* __restrict__ il,
                          uint2* __restrict__ wh, uint2* __restrict__ wl)
{
    const int NI = TOKENS * EMBED / 4;
    const int NW = EMBED * EMBED / 4;
    int i = blockIdx.x * 256 + threadIdx.x;

    const float4* src;
    uint2 *H, *L;
    if (i < 3 * NI) {
        int seg = i / NI;
        int off = i - seg * NI;
        src = (seg == 0 ? q : seg == 1 ? k : v) + off;
        H = ih + (size_t)seg * NI + off;
        L = il + (size_t)seg * NI + off;
    } else {
        int j = i - 3 * NI;
        int seg = j / NW;
        int off = j - seg * NW;
        src = (seg == 0 ? wq : seg == 1 ? wk : seg == 2 ? wv : wo) + off;
        H = wh + (size_t)seg * NW + off;
        L = wl + (size_t)seg * NW + off;
    }
    float4 val = *src;
    uint2 Hv, Lv;
    Hv.x = split2(val.x, val.y, Lv.x);
    Hv.y = split2(val.z, val.w, Lv.y);
    *H = Hv;
    *L = Lv;
}

// ---------------------------------------------------------------------------
// bf16x3 tensor-core GEMM (R6-proven config): 128x128 CTA, BK=32, 8 warps,
// 3-stage cp.async (32KB/stage), __launch_bounds__(256,2) -> 2 CTAs/SM.
// ---------------------------------------------------------------------------
#define GEMM_SMEM (3 * 4 * 8192)   // 96KB; x2 CTAs = 192KB

__global__ __launch_bounds__(256, 2)
void gemm_bf16x3_kernel(const __nv_bfloat16* __restrict__ Ahi_b,
                        const __nv_bfloat16* __restrict__ Alo_b,
                        int strideAz,
                        const __nv_bfloat16* __restrict__ Whi_b,
                        const __nv_bfloat16* __restrict__ Wlo_b,
                        int strideWz,
                        const float* __restrict__ b0, const float* __restrict__ b1,
                        const float* __restrict__ b2,
                        float* __restrict__ Cf,
                        __nv_bfloat16* __restrict__ H0, __nv_bfloat16* __restrict__ H1,
                        __nv_bfloat16* __restrict__ H2,
                        __nv_bfloat16* __restrict__ L0, __nv_bfloat16* __restrict__ L1,
                        __nv_bfloat16* __restrict__ L2)
{
    extern __shared__ char sm[];
    const uint32_t sb = smem_u32(sm);
    const int tid  = threadIdx.x;
    const int wid  = tid >> 5;
    const int lane = tid & 31;

    const int z = blockIdx.z;
    const __nv_bfloat16* Ahi = Ahi_b + (size_t)z * strideAz;
    const __nv_bfloat16* Alo = Alo_b + (size_t)z * strideAz;
    const __nv_bfloat16* Whi = Whi_b + (size_t)z * strideWz;
    const __nv_bfloat16* Wlo = Wlo_b + (size_t)z * strideWz;
    const float* bias = (z == 0) ? b0 : (z == 1) ? b1 : b2;

    const int row0 = blockIdx.y * 128;
    const int col0 = blockIdx.x * 128;
    const int wm = (wid & 1) * 64;
    const int wn = (wid >> 1) * 32;

    const int lm = tid >> 1;
    const int lc = (tid & 1) * 2;
    const __nv_bfloat16* gAh = Ahi + (size_t)(row0 + lm) * EMBED + lc * 8;
    const __nv_bfloat16* gAl = Alo + (size_t)(row0 + lm) * EMBED + lc * 8;
    const __nv_bfloat16* gWh = Whi + (size_t)(col0 + lm) * EMBED + lc * 8;
    const __nv_bfloat16* gWl = Wlo + (size_t)(col0 + lm) * EMBED + lc * 8;
    const uint32_t s0 = swz(lm, lc);
    const uint32_t s1 = swz(lm, lc + 1);

    float acc[4][4][4];
#pragma unroll
    for (int i = 0; i < 4; i++)
#pragma unroll
        for (int j = 0; j < 4; j++)
#pragma unroll
            for (int q = 0; q < 4; q++) acc[i][j][q] = 0.0f;

    auto issue = [&](int ch) {
        const uint32_t st = sb + (uint32_t)(ch % 3) * 32768u;
        const int ko = ch * 32;
        CP16(st             + s0, gAh + ko);
        CP16(st             + s1, gAh + ko + 8);
        CP16(st +     8192u + s0, gAl + ko);
        CP16(st +     8192u + s1, gAl + ko + 8);
        CP16(st + 2 * 8192u + s0, gWh + ko);
        CP16(st + 2 * 8192u + s1, gWh + ko + 8);
        CP16(st + 3 * 8192u + s0, gWl + ko);
        CP16(st + 3 * 8192u + s1, gWl + ko + 8);
    };

    issue(0); CP_COMMIT();
    issue(1); CP_COMMIT();

    const int mA  = wm + (lane & 7) + ((lane >> 3) & 1) * 8;
    const int cA  = (lane >> 4);
    const int nB4 = wn + (lane & 7) + ((lane >> 4) << 3);
    const int cB4 = ((lane >> 3) & 1);

    const int NCHUNK = EMBED / 32;
    for (int ch = 0; ch < NCHUNK; ch++) {
        if (ch + 1 < NCHUNK) { CP_WAIT(1); } else { CP_WAIT(0); }
        __syncthreads();
        if (ch + 2 < NCHUNK) { issue(ch + 2); CP_COMMIT(); }

        const uint32_t stb = sb + (uint32_t)(ch % 3) * 32768u;
#pragma unroll
        for (int ks = 0; ks < 2; ks++) {
            uint32_t ah[4][4], al[4][4], bh[4][2], bl[4][2];
            const int ca = ks * 2 + cA;
            const int cb = ks * 2 + cB4;
#pragma unroll
            for (int i = 0; i < 4; i++) {
                LDSM4(ah[i], stb        + swz(mA + i * 16, ca));
                LDSM4(al[i], stb + 8192 + swz(mA + i * 16, ca));
            }
#pragma unroll
            for (int jj = 0; jj < 2; jj++) {
                uint32_t t[4];
                LDSM4(t, stb + 2 * 8192 + swz(nB4 + jj * 16, cb));
                bh[2 * jj][0] = t[0]; bh[2 * jj][1] = t[1];
                bh[2 * jj + 1][0] = t[2]; bh[2 * jj + 1][1] = t[3];
                LDSM4(t, stb + 3 * 8192 + swz(nB4 + jj * 16, cb));
                bl[2 * jj][0] = t[0]; bl[2 * jj][1] = t[1];
                bl[2 * jj + 1][0] = t[2]; bl[2 * jj + 1][1] = t[3];
            }
#pragma unroll
            for (int i = 0; i < 4; i++)
#pragma unroll
                for (int j = 0; j < 4; j++) {
                    MMA16816(acc[i][j], ah[i], bh[j]);
                    MMA16816(acc[i][j], al[i], bh[j]);
                    MMA16816(acc[i][j], ah[i], bl[j]);
                }
        }
    }

    const int mrow = row0 + wm + (lane >> 2);
    const int ncol = col0 + wn + (lane & 3) * 2;
    if (H0) {
        __nv_bfloat16* Hi = (z == 0) ? H0 : (z == 1) ? H1 : H2;
        __nv_bfloat16* Lo = (z == 0) ? L0 : (z == 1) ? L1 : L2;
#pragma unroll
        for (int i = 0; i < 4; i++)
#pragma unroll
            for (int j = 0; j < 4; j++) {
                const int r  = mrow + i * 16;
                const int cn = ncol + j * 8;
                const float bx = bias[cn], by = bias[cn + 1];
                uint32_t l0v, l1v;
                uint32_t h0v = split2(acc[i][j][0] + bx, acc[i][j][1] + by, l0v);
                uint32_t h1v = split2(acc[i][j][2] + bx, acc[i][j][3] + by, l1v);
                *(uint32_t*)(Hi + (size_t)r       * EMBED + cn) = h0v;
                *(uint32_t*)(Lo + (size_t)r       * EMBED + cn) = l0v;
                *(uint32_t*)(Hi + (size_t)(r + 8) * EMBED + cn) = h1v;
                *(uint32_t*)(Lo + (size_t)(r + 8) * EMBED + cn) = l1v;
            }
    } else {
#pragma unroll
        for (int i = 0; i < 4; i++)
#pragma unroll
            for (int j = 0; j < 4; j++) {
                const int r  = mrow + i * 16;
                const int cn = ncol + j * 8;
                const float bx = bias[cn], by = bias[cn + 1];
                float2 v0 = make_float2(acc[i][j][0] + bx, acc[i][j][1] + by);
                float2 v1 = make_float2(acc[i][j][2] + bx, acc[i][j][3] + by);
                *(float2*)(Cf + (size_t)r       * EMBED + cn) = v0;
                *(float2*)(Cf + (size_t)(r + 8) * EMBED + cn) = v1;
            }
    }
}

// ---------------------------------------------------------------------------
// Tensor-core flash attention (R8-proven): QK^T 2-term (QhKh + QlKh),
// PV 3-term. K-tile 64, 2-stage cp.async. stage: Kh Vh Vl (8K ea) + mask.
// ---------------------------------------------------------------------------
#define KT 64
#define ATT_STAGE (3 * 8192 + 256)
#define ATT_SMEM  (2 * 16384 + 2 * ATT_STAGE)   // 82432 B; 2 CTAs/SM

__global__ __launch_bounds__(256, 2)
void attention_tc_kernel(const __nv_bfloat16* __restrict__ Qh,
                         const __nv_bfloat16* __restrict__ Ql,
                         const __nv_bfloat16* __restrict__ Kh,
                         const __nv_bfloat16* __restrict__ Vh,
                         const __nv_bfloat16* __restrict__ Vl,
                         const int* __restrict__ mask,
                         __nv_bfloat16* __restrict__ Ohi,
                         __nv_bfloat16* __restrict__ Olo)
{
    extern __shared__ char sm[];
    const uint32_t sb = smem_u32(sm);
    const uint32_t oQh = 0, oQl = 16384, oStage = 32768;
    const int tid  = threadIdx.x;
    const int lane = tid & 31;
    const int w    = tid >> 5;
    const int qt   = blockIdx.x;
    const int h    = blockIdx.y;
    const int b    = blockIdx.z;
    const int colh = h * HEAD_DIM;
    const size_t base = (size_t)b * SEQ * EMBED;
    const float CEXP = 1.4426950408889634f / 32.0f;

    auto issueKV = [&](int kt) {
        const uint32_t ksb = sb + oStage + (uint32_t)(kt & 1) * ATT_STAGE;
#pragma unroll
        for (int it = 0; it < 2; it++) {
            int idx = tid + it * 256;
            int r = idx >> 3, u = idx & 7;
            size_t g = base + (size_t)(kt * KT + r) * EMBED + colh + u * 8;
            uint32_t so = sw128(r, u);
            CP16(ksb             + so, Kh + g);
            CP16(ksb +     8192u + so, Vh + g);
            CP16(ksb + 2 * 8192u + so, Vl + g);
        }
        if (tid < 16)
            CP16(ksb + 3 * 8192u + (uint32_t)tid * 16u,
                 mask + b * SEQ + kt * KT + tid * 4);
    };

    issueKV(0); CP_COMMIT();

#pragma unroll
    for (int it = 0; it < 4; it++) {
        int idx = tid + it * 256;
        int r = idx >> 3, u = idx & 7;
        size_t g = base + (size_t)(qt * 128 + r) * EMBED + colh + u * 8;
        uint32_t so = sw128(r, u);
        *(uint4*)(sm + oQh + so) = *(const uint4*)(Qh + g);
        *(uint4*)(sm + oQl + so) = *(const uint4*)(Ql + g);
    }

    const int q0 = w * 16;
    float o[8][4];
#pragma unroll
    for (int j = 0; j < 8; j++)
#pragma unroll
        for (int q = 0; q < 4; q++) o[j][q] = 0.0f;
    const float NEG_INF = __int_as_float(0xff800000);
    float mr0 = NEG_INF, mr1 = NEG_INF, lr0 = 0.0f, lr1 = 0.0f;

    const uint32_t rowA = (uint32_t)(q0 + (lane & 15));
    const uint32_t uA   = (uint32_t)(lane >> 4);
    const uint32_t rowB = (uint32_t)((lane & 7) + ((lane >> 4) << 3));
    const uint32_t uB   = (uint32_t)((lane >> 3) & 1);
    const uint32_t rowV = (uint32_t)((lane & 7) + (((lane >> 3) & 1) << 3));
    const uint32_t uV   = (uint32_t)(lane >> 4);

    const int NITER = SEQ / KT;
    for (int kt = 0; kt < NITER; kt++) {
        if (kt + 1 < NITER) { issueKV(kt + 1); CP_COMMIT(); CP_WAIT(1); }
        else                { CP_WAIT(0); }
        __syncthreads();

        const uint32_t stg = sb + oStage + (uint32_t)(kt & 1) * ATT_STAGE;
        const uint32_t oKh = stg, oVh = stg + 8192, oVl = stg + 2 * 8192;
        const int* msk = (const int*)(sm + (oStage + (uint32_t)(kt & 1) * ATT_STAGE
                                            + 3 * 8192));

        // ---- S = Q K^T (2-term) ----
        float s[8][4];
#pragma unroll
        for (int j = 0; j < 8; j++)
#pragma unroll
            for (int q = 0; q < 4; q++) s[j][q] = 0.0f;

#pragma unroll
        for (int ks = 0; ks < 4; ks++) {
            uint32_t ah[4], al[4];
            const uint32_t ua = uA + ks * 2;
            const uint32_t aoff = rowA * 128 + ((ua ^ (rowA & 7)) << 4);
            LDSM4(ah, sb + oQh + aoff);
            LDSM4(al, sb + oQl + aoff);
#pragma unroll
            for (int np = 0; np < 4; np++) {
                const uint32_t rb = rowB + np * 16;
                const uint32_t ub = uB + ks * 2;
                const uint32_t boff = rb * 128 + ((ub ^ (rb & 7)) << 4);
                uint32_t kh4[4];
                LDSM4(kh4, oKh + boff);
                MMA16816(s[2 * np],     ah, kh4);
                MMA16816(s[2 * np],     al, kh4);
                MMA16816(s[2 * np + 1], ah, kh4 + 2);
                MMA16816(s[2 * np + 1], al, kh4 + 2);
            }
        }

        // ---- mask + online softmax ----
        const int cb2 = (lane & 3) * 2;
        float mx0 = NEG_INF, mx1 = NEG_INF;
#pragma unroll
        for (int j = 0; j < 8; j++) {
            const int col = j * 8 + cb2;
            const int m0v = msk[col], m1v = msk[col + 1];
            if (!m0v) { s[j][0] = -1e20f; s[j][2] = -1e20f; }
            if (!m1v) { s[j][1] = -1e20f; s[j][3] = -1e20f; }
            mx0 = fmaxf(mx0, fmaxf(s[j][0], s[j][1]));
            mx1 = fmaxf(mx1, fmaxf(s[j][2], s[j][3]));
        }
        mx0 = fmaxf(mx0, __shfl_xor_sync(0xffffffffu, mx0, 1));
        mx0 = fmaxf(mx0, __shfl_xor_sync(0xffffffffu, mx0, 2));
        mx1 = fmaxf(mx1, __shfl_xor_sync(0xffffffffu, mx1, 1));
        mx1 = fmaxf(mx1, __shfl_xor_sync(0xffffffffu, mx1, 2));

        const float mn0 = fmaxf(mr0, mx0);
        const float mn1 = fmaxf(mr1, mx1);
        const float c0 = fast_exp2((mr0 - mn0) * CEXP);
        const float c1 = fast_exp2((mr1 - mn1) * CEXP);
        mr0 = mn0; mr1 = mn1;

        float sum0 = 0.0f, sum1 = 0.0f;
#pragma unroll
        for (int j = 0; j < 8; j++) {
            s[j][0] = fast_exp2((s[j][0] - mn0) * CEXP);
            s[j][1] = fast_exp2((s[j][1] - mn0) * CEXP);
            s[j][2] = fast_exp2((s[j][2] - mn1) * CEXP);
            s[j][3] = fast_exp2((s[j][3] - mn1) * CEXP);
            sum0 += s[j][0] + s[j][1];
            sum1 += s[j][2] + s[j][3];
        }
        sum0 += __shfl_xor_sync(0xffffffffu, sum0, 1);
        sum0 += __shfl_xor_sync(0xffffffffu, sum0, 2);
        sum1 += __shfl_xor_sync(0xffffffffu, sum1, 1);
        sum1 += __shfl_xor_sync(0xffffffffu, sum1, 2);
        lr0 = lr0 * c0 + sum0;
        lr1 = lr1 * c1 + sum1;
#pragma unroll
        for (int jd = 0; jd < 8; jd++) {
            o[jd][0] *= c0; o[jd][1] *= c0;
            o[jd][2] *= c1; o[jd][3] *= c1;
        }

        // ---- O += P V (3-term) ----
#pragma unroll
        for (int kk = 0; kk < 4; kk++) {
            uint32_t ph[4], pl[4];
            ph[0] = split2(s[2 * kk][0],     s[2 * kk][1],     pl[0]);
            ph[1] = split2(s[2 * kk][2],     s[2 * kk][3],     pl[1]);
            ph[2] = split2(s[2 * kk + 1][0], s[2 * kk + 1][1], pl[2]);
            ph[3] = split2(s[2 * kk + 1][2], s[2 * kk + 1][3], pl[3]);
            const uint32_t k0 = kk * 16;
#pragma unroll
            for (int jdp = 0; jdp < 4; jdp++) {
                const uint32_t rv = k0 + rowV;
                const uint32_t uv = jdp * 2 + uV;
                const uint32_t voff = rv * 128 + ((uv ^ (rv & 7)) << 4);
                uint32_t bh4[4], bl4[4];
                LDSM4T(bh4, oVh + voff);
                LDSM4T(bl4, oVl + voff);
                MMA16816(o[2 * jdp],     ph, bh4);
                MMA16816(o[2 * jdp],     pl, bh4);
                MMA16816(o[2 * jdp],     ph, bl4);
                MMA16816(o[2 * jdp + 1], ph, bh4 + 2);
                MMA16816(o[2 * jdp + 1], pl, bh4 + 2);
                MMA16816(o[2 * jdp + 1], ph, bl4 + 2);
            }
        }
        __syncthreads();
    }

    const float inv0 = 1.0f / lr0;
    const float inv1 = 1.0f / lr1;
    const int r0g = qt * 128 + q0 + (lane >> 2);
    const int cbe = (lane & 3) * 2;
#pragma unroll
    for (int jd = 0; jd < 8; jd++) {
        const int cn = colh + jd * 8 + cbe;
        uint32_t l0v, l1v;
        uint32_t h0v = split2(o[jd][0] * inv0, o[jd][1] * inv0, l0v);
        uint32_t h1v = split2(o[jd][2] * inv1, o[jd][3] * inv1, l1v);
        size_t i0 = base + (size_t)r0g * EMBED + cn;
        size_t i1 = base + (size_t)(r0g + 8) * EMBED + cn;
        *(uint32_t*)(Ohi + i0) = h0v;
        *(uint32_t*)(Olo + i0) = l0v;
        *(uint32_t*)(Ohi + i1) = h1v;
        *(uint32_t*)(Olo + i1) = l1v;
    }
}

// ---------------------------------------------------------------------------
// Launch
// ---------------------------------------------------------------------------
extern "C" void kernel_launch(void* const* d_in, const int* in_sizes, int n_in,
                              void* d_out, int out_size)
{
    const float* query = (const float*)d_in[0];
    const float* key   = (const float*)d_in[1];
    const float* value = (const float*)d_in[2];
    const int*   mask  = (const int*)  d_in[3];
    const float* Wq    = (const float*)d_in[4];
    const float* bq    = (const float*)d_in[5];
    const float* Wk    = (const float*)d_in[6];
    const float* bk    = (const float*)d_in[7];
    const float* Wv    = (const float*)d_in[8];
    const float* bv    = (const float*)d_in[9];
    const float* Wo    = (const float*)d_in[10];
    const float* bo    = (const float*)d_in[11];
    float* out = (float*)d_out;

    __nv_bfloat16 *ih, *il, *wh, *wl, *aoh, *aol;
    __nv_bfloat16 *qh, *ql, *kh, *kl, *vh, *vl;
    cudaGetSymbolAddress((void**)&ih,  g_in_hi);
    cudaGetSymbolAddress((void**)&il,  g_in_lo);
    cudaGetSymbolAddress((void**)&wh,  g_w_hi);
    cudaGetSymbolAddress((void**)&wl,  g_w_lo);
    cudaGetSymbolAddress((void**)&aoh, g_ao_hi);
    cudaGetSymbolAddress((void**)&aol, g_ao_lo);
    cudaGetSymbolAddress((void**)&qh,  g_qh);
    cudaGetSymbolAddress((void**)&ql,  g_ql);
    cudaGetSymbolAddress((void**)&kh,  g_kh);
    cudaGetSymbolAddress((void**)&kl,  g_kl);
    cudaGetSymbolAddress((void**)&vh,  g_vh);
    cudaGetSymbolAddress((void**)&vl,  g_vl);

    cudaFuncSetAttribute(gemm_bf16x3_kernel,
                         cudaFuncAttributeMaxDynamicSharedMemorySize, GEMM_SMEM);
    cudaFuncSetAttribute(attention_tc_kernel,
                         cudaFuncAttributeMaxDynamicSharedMemorySize, ATT_SMEM);

    // One fused split pass
    const int NI = TOKENS * EMBED / 4;
    const int NW = EMBED * EMBED / 4;
    cvt_split_all_kernel<<<(3 * NI + 4 * NW) / 256, 256>>>(
        (const float4*)query, (const float4*)key, (const float4*)value,
        (const float4*)Wq, (const float4*)Wk, (const float4*)Wv, (const float4*)Wo,
        (uint2*)ih, (uint2*)il, (uint2*)wh, (uint2*)wl);

    // QKV projections -> bf16 hi/lo planes
    gemm_bf16x3_kernel<<<dim3(EMBED / 128, TOKENS / 128, 3), 256, GEMM_SMEM>>>(
        ih, il, TOKENS * EMBED, wh, wl, EMBED * EMBED,
        bq, bk, bv, nullptr, qh, kh, vh, ql, kl, vl);

    // Tensor-core flash attention (Kl plane unused)
    attention_tc_kernel<<<dim3(SEQ / 128, HEADS, BATCH), 256, ATT_SMEM>>>(
        qh, ql, kh, vh, vl, mask, aoh, aol);

    // Output projection -> fp32
    gemm_bf16x3_kernel<<<dim3(EMBED / 128, TOKENS / 128, 1), 256, GEMM_SMEM>>>(
        aoh, aol, 0, wh + (size_t)3 * EMBED * EMBED, wl + (size_t)3 * EMBED * EMBED, 0,
        bo, bo, bo, out,
        nullptr, nullptr, nullptr, nullptr, nullptr, nullptr);
}

// round 12
// speedup vs baseline: 2.2837x; 1.3807x over previous
#include <cuda_runtime.h>
#include <cuda_fp16.h>
#include <cstdint>
#include <math.h>

#define EMBED    1024
#define HEADS    16
#define HEAD_DIM 64
#define BATCH    2
#define SEQ      2048
#define TOKENS   (BATCH * SEQ)

// ---------------------------------------------------------------------------
// Scratch (device globals)
// ---------------------------------------------------------------------------
__device__ __half g_in_hi[3 * TOKENS * EMBED];
__device__ __half g_in_lo[3 * TOKENS * EMBED];
__device__ __half g_w_h  [4 * EMBED * EMBED];
__device__ __half g_qh[TOKENS * EMBED];
__device__ __half g_kh[TOKENS * EMBED];
__device__ __half g_vh[TOKENS * EMBED];
__device__ __half g_ao_hi[TOKENS * EMBED];
__device__ __half g_ao_lo[TOKENS * EMBED];

__device__ __forceinline__ uint32_t smem_u32(const void* p) {
    uint32_t a;
    asm("{ .reg .u64 t; cvta.to.shared.u64 t, %1; cvt.u32.u64 %0, t; }"
        : "=r"(a) : "l"(p));
    return a;
}
__device__ __forceinline__ float fast_exp2(float x) {
    float y;
    asm("ex2.approx.f32 %0, %1;" : "=f"(y) : "f"(x));
    return y;
}
// fp16 hi/lo split: hi+lo reproduces the fp32 value to ~2^-23
__device__ __forceinline__ uint32_t split2h(float a, float b, uint32_t& lo) {
    __half2 h = __floats2half2_rn(a, b);
    __half2 l = __floats2half2_rn(a - __half2float(__low2half(h)),
                                  b - __half2float(__high2half(h)));
    lo = *reinterpret_cast<uint32_t*>(&l);
    return *reinterpret_cast<uint32_t*>(&h);
}
__device__ __forceinline__ uint32_t cvt2h(float a, float b) {
    __half2 h = __floats2half2_rn(a, b);
    return *reinterpret_cast<uint32_t*>(&h);
}

#define LDSM4(r, a) \
    asm volatile("ldmatrix.sync.aligned.m8n8.x4.shared.b16 {%0,%1,%2,%3}, [%4];" \
                 : "=r"((r)[0]), "=r"((r)[1]), "=r"((r)[2]), "=r"((r)[3]) : "r"(a))
#define LDSM4T(r, a) \
    asm volatile("ldmatrix.sync.aligned.m8n8.x4.trans.shared.b16 {%0,%1,%2,%3}, [%4];" \
                 : "=r"((r)[0]), "=r"((r)[1]), "=r"((r)[2]), "=r"((r)[3]) : "r"(a))
#define MMA16816(d, a, b) \
    asm volatile("mma.sync.aligned.m16n8k16.row.col.f32.f16.f16.f32 " \
                 "{%0,%1,%2,%3}, {%4,%5,%6,%7}, {%8,%9}, {%0,%1,%2,%3};" \
                 : "+f"((d)[0]), "+f"((d)[1]), "+f"((d)[2]), "+f"((d)[3]) \
                 : "r"((a)[0]), "r"((a)[1]), "r"((a)[2]), "r"((a)[3]), \
                   "r"((b)[0]), "r"((b)[1]))
#define CP16(dst, src) \
    asm volatile("cp.async.ca.shared.global [%0], [%1], 16;" \
                 :: "r"(dst), "l"(src) : "memory")
#define CP_COMMIT() asm volatile("cp.async.commit_group;" ::: "memory")
#define CP_WAIT(n)  asm volatile("cp.async.wait_group %0;" :: "n"(n) : "memory")

// GEMM smem swizzle: 2 logical 32-elem rows per 128B line
__device__ __forceinline__ uint32_t swz(int m, int c) {
    return (uint32_t)((m >> 1) * 128 + (((((m & 1) << 2) | c) ^ ((m >> 1) & 7)) << 4));
}
// attention smem swizzle: 64-elem rows, 128B lines
__device__ __forceinline__ uint32_t sw128(int m, int u) {
    return (uint32_t)(m * 128 + ((u ^ (m & 7)) << 4));
}

// ---------------------------------------------------------------------------
// Fused fp32 -> fp16 split pass: inputs -> hi+lo planes, weights -> hi only
// ---------------------------------------------------------------------------
__global__ __launch_bounds__(256)
void cvt_split_all_kernel(const float4* __restrict__ q, const float4* __restrict__ k,
                          const float4* __restrict__ v,
                          const float4* __restrict__ wq, const float4* __restrict__ wk,
                          const float4* __restrict__ wv, const float4* __restrict__ wo,
                          uint2* __restrict__ ih, uint2* __restrict__ il,
                          uint2* __restrict__ wh)
{
    const int NI = TOKENS * EMBED / 4;
    const int NW = EMBED * EMBED / 4;
    int i = blockIdx.x * 256 + threadIdx.x;

    if (i < 3 * NI) {
        int seg = i / NI;
        int off = i - seg * NI;
        float4 val = *((seg == 0 ? q : seg == 1 ? k : v) + off);
        uint2 Hv, Lv;
        Hv.x = split2h(val.x, val.y, Lv.x);
        Hv.y = split2h(val.z, val.w, Lv.y);
        ih[(size_t)seg * NI + off] = Hv;
        il[(size_t)seg * NI + off] = Lv;
    } else {
        int j = i - 3 * NI;
        int seg = j / NW;
        int off = j - seg * NW;
        float4 val = *((seg == 0 ? wq : seg == 1 ? wk : seg == 2 ? wv : wo) + off);
        uint2 Hv;
        Hv.x = cvt2h(val.x, val.y);
        Hv.y = cvt2h(val.z, val.w);
        wh[(size_t)seg * NW + off] = Hv;
    }
}

// ---------------------------------------------------------------------------
// fp16 2-term tensor-core GEMM: C = (Ah+Al) @ Wh^T + bias.
// 128x128 CTA, BK=32, 8 warps (64x32), 3-stage cp.async, 2 CTAs/SM.
// smem/stage: Ah 8K | Al 8K | Wh 8K = 24KB.
// ---------------------------------------------------------------------------
#define G_STAGE 24576
#define GEMM_SMEM (3 * G_STAGE)   // 72KB; x2 CTAs = 144KB

__global__ __launch_bounds__(256, 2)
void gemm_f16x2_kernel(const __half* __restrict__ Ah_b, const __half* __restrict__ Al_b,
                       int strideAz,
                       const __half* __restrict__ Wh_b, int strideWz,
                       const float* __restrict__ b0, const float* __restrict__ b1,
                       const float* __restrict__ b2,
                       float* __restrict__ Cf,
                       __half* __restrict__ H0, __half* __restrict__ H1,
                       __half* __restrict__ H2)
{
    extern __shared__ char sm[];
    const uint32_t sb = smem_u32(sm);
    const int tid  = threadIdx.x;
    const int wid  = tid >> 5;
    const int lane = tid & 31;

    const int z = blockIdx.z;
    const __half* Ah = Ah_b + (size_t)z * strideAz;
    const __half* Al = Al_b + (size_t)z * strideAz;
    const __half* Wh = Wh_b + (size_t)z * strideWz;
    const float* bias = (z == 0) ? b0 : (z == 1) ? b1 : b2;

    const int row0 = blockIdx.y * 128;
    const int col0 = blockIdx.x * 128;
    const int wm = (wid & 1) * 64;
    const int wn = (wid >> 1) * 32;

    const int lm = tid >> 1;
    const int lc = (tid & 1) * 2;
    const __half* gAh = Ah + (size_t)(row0 + lm) * EMBED + lc * 8;
    const __half* gAl = Al + (size_t)(row0 + lm) * EMBED + lc * 8;
    const __half* gWh = Wh + (size_t)(col0 + lm) * EMBED + lc * 8;
    const uint32_t s0 = swz(lm, lc);
    const uint32_t s1 = swz(lm, lc + 1);

    float acc[4][4][4];
#pragma unroll
    for (int i = 0; i < 4; i++)
#pragma unroll
        for (int j = 0; j < 4; j++)
#pragma unroll
            for (int q = 0; q < 4; q++) acc[i][j][q] = 0.0f;

    auto issue = [&](int ch) {
        const uint32_t st = sb + (uint32_t)(ch % 3) * (uint32_t)G_STAGE;
        const int ko = ch * 32;
        CP16(st             + s0, gAh + ko);
        CP16(st             + s1, gAh + ko + 8);
        CP16(st +     8192u + s0, gAl + ko);
        CP16(st +     8192u + s1, gAl + ko + 8);
        CP16(st + 2 * 8192u + s0, gWh + ko);
        CP16(st + 2 * 8192u + s1, gWh + ko + 8);
    };

    issue(0); CP_COMMIT();
    issue(1); CP_COMMIT();

    const int mA  = wm + (lane & 7) + ((lane >> 3) & 1) * 8;
    const int cA  = (lane >> 4);
    const int nB4 = wn + (lane & 7) + ((lane >> 4) << 3);
    const int cB4 = ((lane >> 3) & 1);

    const int NCHUNK = EMBED / 32;
    for (int ch = 0; ch < NCHUNK; ch++) {
        if (ch + 1 < NCHUNK) { CP_WAIT(1); } else { CP_WAIT(0); }
        __syncthreads();
        if (ch + 2 < NCHUNK) { issue(ch + 2); CP_COMMIT(); }

        const uint32_t stb = sb + (uint32_t)(ch % 3) * (uint32_t)G_STAGE;
#pragma unroll
        for (int ks = 0; ks < 2; ks++) {
            uint32_t ah[4][4], al[4][4], bh[4][2];
            const int ca = ks * 2 + cA;
            const int cb = ks * 2 + cB4;
#pragma unroll
            for (int i = 0; i < 4; i++) {
                LDSM4(ah[i], stb        + swz(mA + i * 16, ca));
                LDSM4(al[i], stb + 8192 + swz(mA + i * 16, ca));
            }
#pragma unroll
            for (int jj = 0; jj < 2; jj++) {
                uint32_t t[4];
                LDSM4(t, stb + 2 * 8192 + swz(nB4 + jj * 16, cb));
                bh[2 * jj][0] = t[0]; bh[2 * jj][1] = t[1];
                bh[2 * jj + 1][0] = t[2]; bh[2 * jj + 1][1] = t[3];
            }
#pragma unroll
            for (int i = 0; i < 4; i++)
#pragma unroll
                for (int j = 0; j < 4; j++) {
                    MMA16816(acc[i][j], ah[i], bh[j]);
                    MMA16816(acc[i][j], al[i], bh[j]);
                }
        }
    }

    const int mrow = row0 + wm + (lane >> 2);
    const int ncol = col0 + wn + (lane & 3) * 2;
    if (H0) {
        __half* Hi = (z == 0) ? H0 : (z == 1) ? H1 : H2;
#pragma unroll
        for (int i = 0; i < 4; i++)
#pragma unroll
            for (int j = 0; j < 4; j++) {
                const int r  = mrow + i * 16;
                const int cn = ncol + j * 8;
                const float bx = bias[cn], by = bias[cn + 1];
                *(uint32_t*)(Hi + (size_t)r       * EMBED + cn) =
                    cvt2h(acc[i][j][0] + bx, acc[i][j][1] + by);
                *(uint32_t*)(Hi + (size_t)(r + 8) * EMBED + cn) =
                    cvt2h(acc[i][j][2] + bx, acc[i][j][3] + by);
            }
    } else {
#pragma unroll
        for (int i = 0; i < 4; i++)
#pragma unroll
            for (int j = 0; j < 4; j++) {
                const int r  = mrow + i * 16;
                const int cn = ncol + j * 8;
                const float bx = bias[cn], by = bias[cn + 1];
                float2 v0 = make_float2(acc[i][j][0] + bx, acc[i][j][1] + by);
                float2 v1 = make_float2(acc[i][j][2] + bx, acc[i][j][3] + by);
                *(float2*)(Cf + (size_t)r       * EMBED + cn) = v0;
                *(float2*)(Cf + (size_t)(r + 8) * EMBED + cn) = v1;
            }
    }
}

// ---------------------------------------------------------------------------
// fp16 tensor-core flash attention:
//   S = Qh Kh^T        (1-term; Q/K truncation errors attenuated by /32)
//   O += (Ph+Pl) Vh    (2-term; P captured exactly, only V truncation)
// K-tile 64, 2-stage cp.async. stage: Kh 8K | Vh 8K | mask 256B.
// ---------------------------------------------------------------------------
#define KT 64
#define ATT_STAGE (2 * 8192 + 256)
#define ATT_SMEM  (16384 + 2 * ATT_STAGE)   // 49664 B

__global__ __launch_bounds__(256, 2)
void attention_tc_kernel(const __half* __restrict__ Qh,
                         const __half* __restrict__ Kh,
                         const __half* __restrict__ Vh,
                         const int* __restrict__ mask,
                         __half* __restrict__ Ohi,
                         __half* __restrict__ Olo)
{
    extern __shared__ char sm[];
    const uint32_t sb = smem_u32(sm);
    const uint32_t oQ = 0, oStage = 16384;
    const int tid  = threadIdx.x;
    const int lane = tid & 31;
    const int w    = tid >> 5;
    const int qt   = blockIdx.x;
    const int h    = blockIdx.y;
    const int b    = blockIdx.z;
    const int colh = h * HEAD_DIM;
    const size_t base = (size_t)b * SEQ * EMBED;
    const float CEXP = 1.4426950408889634f / 32.0f;

    auto issueKV = [&](int kt) {
        const uint32_t ksb = sb + oStage + (uint32_t)(kt & 1) * ATT_STAGE;
#pragma unroll
        for (int it = 0; it < 2; it++) {
            int idx = tid + it * 256;
            int r = idx >> 3, u = idx & 7;
            size_t g = base + (size_t)(kt * KT + r) * EMBED + colh + u * 8;
            uint32_t so = sw128(r, u);
            CP16(ksb         + so, Kh + g);
            CP16(ksb + 8192u + so, Vh + g);
        }
        if (tid < 16)
            CP16(ksb + 2 * 8192u + (uint32_t)tid * 16u,
                 mask + b * SEQ + kt * KT + tid * 4);
    };

    issueKV(0); CP_COMMIT();

    // Load Q tile (hi plane only)
#pragma unroll
    for (int it = 0; it < 4; it++) {
        int idx = tid + it * 256;
        int r = idx >> 3, u = idx & 7;
        size_t g = base + (size_t)(qt * 128 + r) * EMBED + colh + u * 8;
        *(uint4*)(sm + oQ + sw128(r, u)) = *(const uint4*)(Qh + g);
    }

    const int q0 = w * 16;
    float o[8][4];
#pragma unroll
    for (int j = 0; j < 8; j++)
#pragma unroll
        for (int q = 0; q < 4; q++) o[j][q] = 0.0f;
    const float NEG_INF = __int_as_float(0xff800000);
    float mr0 = NEG_INF, mr1 = NEG_INF, lr0 = 0.0f, lr1 = 0.0f;

    const uint32_t rowA = (uint32_t)(q0 + (lane & 15));
    const uint32_t uA   = (uint32_t)(lane >> 4);
    const uint32_t rowB = (uint32_t)((lane & 7) + ((lane >> 4) << 3));
    const uint32_t uB   = (uint32_t)((lane >> 3) & 1);
    const uint32_t rowV = (uint32_t)((lane & 7) + (((lane >> 3) & 1) << 3));
    const uint32_t uV   = (uint32_t)(lane >> 4);

    const int NITER = SEQ / KT;
    for (int kt = 0; kt < NITER; kt++) {
        if (kt + 1 < NITER) { issueKV(kt + 1); CP_COMMIT(); CP_WAIT(1); }
        else                { CP_WAIT(0); }
        __syncthreads();

        const uint32_t stg = sb + oStage + (uint32_t)(kt & 1) * ATT_STAGE;
        const uint32_t oKh = stg, oVh = stg + 8192;
        const int* msk = (const int*)(sm + (oStage + (uint32_t)(kt & 1) * ATT_STAGE
                                            + 2 * 8192));

        // ---- S = Qh Kh^T (1-term) ----
        float s[8][4];
#pragma unroll
        for (int j = 0; j < 8; j++)
#pragma unroll
            for (int q = 0; q < 4; q++) s[j][q] = 0.0f;

#pragma unroll
        for (int ks = 0; ks < 4; ks++) {
            uint32_t ah[4];
            const uint32_t ua = uA + ks * 2;
            const uint32_t aoff = rowA * 128 + ((ua ^ (rowA & 7)) << 4);
            LDSM4(ah, sb + oQ + aoff);
#pragma unroll
            for (int np = 0; np < 4; np++) {
                const uint32_t rb = rowB + np * 16;
                const uint32_t ub = uB + ks * 2;
                const uint32_t boff = rb * 128 + ((ub ^ (rb & 7)) << 4);
                uint32_t kh4[4];
                LDSM4(kh4, oKh + boff);
                MMA16816(s[2 * np],     ah, kh4);
                MMA16816(s[2 * np + 1], ah, kh4 + 2);
            }
        }

        // ---- mask + online softmax ----
        const int cb2 = (lane & 3) * 2;
        float mx0 = NEG_INF, mx1 = NEG_INF;
#pragma unroll
        for (int j = 0; j < 8; j++) {
            const int col = j * 8 + cb2;
            const int m0v = msk[col], m1v = msk[col + 1];
            if (!m0v) { s[j][0] = -1e20f; s[j][2] = -1e20f; }
            if (!m1v) { s[j][1] = -1e20f; s[j][3] = -1e20f; }
            mx0 = fmaxf(mx0, fmaxf(s[j][0], s[j][1]));
            mx1 = fmaxf(mx1, fmaxf(s[j][2], s[j][3]));
        }
        mx0 = fmaxf(mx0, __shfl_xor_sync(0xffffffffu, mx0, 1));
        mx0 = fmaxf(mx0, __shfl_xor_sync(0xffffffffu, mx0, 2));
        mx1 = fmaxf(mx1, __shfl_xor_sync(0xffffffffu, mx1, 1));
        mx1 = fmaxf(mx1, __shfl_xor_sync(0xffffffffu, mx1, 2));

        const float mn0 = fmaxf(mr0, mx0);
        const float mn1 = fmaxf(mr1, mx1);
        const float c0 = fast_exp2((mr0 - mn0) * CEXP);
        const float c1 = fast_exp2((mr1 - mn1) * CEXP);
        mr0 = mn0; mr1 = mn1;

        float sum0 = 0.0f, sum1 = 0.0f;
#pragma unroll
        for (int j = 0; j < 8; j++) {
            s[j][0] = fast_exp2((s[j][0] - mn0) * CEXP);
            s[j][1] = fast_exp2((s[j][1] - mn0) * CEXP);
            s[j][2] = fast_exp2((s[j][2] - mn1) * CEXP);
            s[j][3] = fast_exp2((s[j][3] - mn1) * CEXP);
            sum0 += s[j][0] + s[j][1];
            sum1 += s[j][2] + s[j][3];
        }
        sum0 += __shfl_xor_sync(0xffffffffu, sum0, 1);
        sum0 += __shfl_xor_sync(0xffffffffu, sum0, 2);
        sum1 += __shfl_xor_sync(0xffffffffu, sum1, 1);
        sum1 += __shfl_xor_sync(0xffffffffu, sum1, 2);
        lr0 = lr0 * c0 + sum0;
        lr1 = lr1 * c1 + sum1;
#pragma unroll
        for (int jd = 0; jd < 8; jd++) {
            o[jd][0] *= c0; o[jd][1] *= c0;
            o[jd][2] *= c1; o[jd][3] *= c1;
        }

        // ---- O += (Ph+Pl) Vh (2-term) ----
#pragma unroll
        for (int kk = 0; kk < 4; kk++) {
            uint32_t ph[4], pl[4];
            ph[0] = split2h(s[2 * kk][0],     s[2 * kk][1],     pl[0]);
            ph[1] = split2h(s[2 * kk][2],     s[2 * kk][3],     pl[1]);
            ph[2] = split2h(s[2 * kk + 1][0], s[2 * kk + 1][1], pl[2]);
            ph[3] = split2h(s[2 * kk + 1][2], s[2 * kk + 1][3], pl[3]);
            const uint32_t k0 = kk * 16;
#pragma unroll
            for (int jdp = 0; jdp < 4; jdp++) {
                const uint32_t rv = k0 + rowV;
                const uint32_t uv = jdp * 2 + uV;
                const uint32_t voff = rv * 128 + ((uv ^ (rv & 7)) << 4);
                uint32_t bh4[4];
                LDSM4T(bh4, oVh + voff);
                MMA16816(o[2 * jdp],     ph, bh4);
                MMA16816(o[2 * jdp],     pl, bh4);
                MMA16816(o[2 * jdp + 1], ph, bh4 + 2);
                MMA16816(o[2 * jdp + 1], pl, bh4 + 2);
            }
        }
        __syncthreads();
    }

    // ---- epilogue: normalize, split fp16 hi/lo for the out-projection ----
    const float inv0 = 1.0f / lr0;
    const float inv1 = 1.0f / lr1;
    const int r0g = qt * 128 + q0 + (lane >> 2);
    const int cbe = (lane & 3) * 2;
#pragma unroll
    for (int jd = 0; jd < 8; jd++) {
        const int cn = colh + jd * 8 + cbe;
        uint32_t l0v, l1v;
        uint32_t h0v = split2h(o[jd][0] * inv0, o[jd][1] * inv0, l0v);
        uint32_t h1v = split2h(o[jd][2] * inv1, o[jd][3] * inv1, l1v);
        size_t i0 = base + (size_t)r0g * EMBED + cn;
        size_t i1 = base + (size_t)(r0g + 8) * EMBED + cn;
        *(uint32_t*)(Ohi + i0) = h0v;
        *(uint32_t*)(Olo + i0) = l0v;
        *(uint32_t*)(Ohi + i1) = h1v;
        *(uint32_t*)(Olo + i1) = l1v;
    }
}

// ---------------------------------------------------------------------------
// Launch
// ---------------------------------------------------------------------------
extern "C" void kernel_launch(void* const* d_in, const int* in_sizes, int n_in,
                              void* d_out, int out_size)
{
    const float* query = (const float*)d_in[0];
    const float* key   = (const float*)d_in[1];
    const float* value = (const float*)d_in[2];
    const int*   mask  = (const int*)  d_in[3];
    const float* Wq    = (const float*)d_in[4];
    const float* bq    = (const float*)d_in[5];
    const float* Wk    = (const float*)d_in[6];
    const float* bk    = (const float*)d_in[7];
    const float* Wv    = (const float*)d_in[8];
    const float* bv    = (const float*)d_in[9];
    const float* Wo    = (const float*)d_in[10];
    const float* bo    = (const float*)d_in[11];
    float* out = (float*)d_out;

    __half *ih, *il, *wh, *qh, *kh, *vh, *aoh, *aol;
    cudaGetSymbolAddress((void**)&ih,  g_in_hi);
    cudaGetSymbolAddress((void**)&il,  g_in_lo);
    cudaGetSymbolAddress((void**)&wh,  g_w_h);
    cudaGetSymbolAddress((void**)&qh,  g_qh);
    cudaGetSymbolAddress((void**)&kh,  g_kh);
    cudaGetSymbolAddress((void**)&vh,  g_vh);
    cudaGetSymbolAddress((void**)&aoh, g_ao_hi);
    cudaGetSymbolAddress((void**)&aol, g_ao_lo);

    cudaFuncSetAttribute(gemm_f16x2_kernel,
                         cudaFuncAttributeMaxDynamicSharedMemorySize, GEMM_SMEM);
    cudaFuncSetAttribute(attention_tc_kernel,
                         cudaFuncAttributeMaxDynamicSharedMemorySize, ATT_SMEM);

    // One fused split pass: inputs -> hi/lo, weights -> hi only
    const int NI = TOKENS * EMBED / 4;
    const int NW = EMBED * EMBED / 4;
    cvt_split_all_kernel<<<(3 * NI + 4 * NW) / 256, 256>>>(
        (const float4*)query, (const float4*)key, (const float4*)value,
        (const float4*)Wq, (const float4*)Wk, (const float4*)Wv, (const float4*)Wo,
        (uint2*)ih, (uint2*)il, (uint2*)wh);

    // QKV projections -> single fp16 plane each
    gemm_f16x2_kernel<<<dim3(EMBED / 128, TOKENS / 128, 3), 256, GEMM_SMEM>>>(
        ih, il, TOKENS * EMBED, wh, EMBED * EMBED,
        bq, bk, bv, nullptr, qh, kh, vh);

    // fp16 flash attention -> hi/lo output planes
    attention_tc_kernel<<<dim3(SEQ / 128, HEADS, BATCH), 256, ATT_SMEM>>>(
        qh, kh, vh, mask, aoh, aol);

    // Output projection -> fp32
    gemm_f16x2_kernel<<<dim3(EMBED / 128, TOKENS / 128, 1), 256, GEMM_SMEM>>>(
        aoh, aol, 0, wh + (size_t)3 * EMBED * EMBED, 0,
        bo, bo, bo, out, nullptr, nullptr, nullptr);
}

// round 16
// speedup vs baseline: 2.7313x; 1.1960x over previous
#include <cuda_runtime.h>
#include <cuda_fp16.h>
#include <cstdint>
#include <math.h>

#define EMBED    1024
#define HEADS    16
#define HEAD_DIM 64
#define BATCH    2
#define SEQ      2048
#define TOKENS   (BATCH * SEQ)

// ---------------------------------------------------------------------------
// Scratch (device globals)
// ---------------------------------------------------------------------------
__device__ __half g_in_h [3 * TOKENS * EMBED];
__device__ __half g_w_h  [4 * EMBED * EMBED];
__device__ __half g_qh[TOKENS * EMBED];
__device__ __half g_kh[TOKENS * EMBED];
__device__ __half g_vh[TOKENS * EMBED];
__device__ __half g_ao_hi[TOKENS * EMBED];
__device__ __half g_ao_lo[TOKENS * EMBED];

__device__ __forceinline__ uint32_t smem_u32(const void* p) {
    uint32_t a;
    asm("{ .reg .u64 t; cvta.to.shared.u64 t, %1; cvt.u32.u64 %0, t; }"
        : "=r"(a) : "l"(p));
    return a;
}
__device__ __forceinline__ float fast_exp2(float x) {
    float y;
    asm("ex2.approx.f32 %0, %1;" : "=f"(y) : "f"(x));
    return y;
}
// fp16 hi/lo split: hi+lo reproduces the fp32 value to ~2^-23
__device__ __forceinline__ uint32_t split2h(float a, float b, uint32_t& lo) {
    __half2 h = __floats2half2_rn(a, b);
    __half2 l = __floats2half2_rn(a - __half2float(__low2half(h)),
                                  b - __half2float(__high2half(h)));
    lo = *reinterpret_cast<uint32_t*>(&l);
    return *reinterpret_cast<uint32_t*>(&h);
}
__device__ __forceinline__ uint32_t cvt2h(float a, float b) {
    __half2 h = __floats2half2_rn(a, b);
    return *reinterpret_cast<uint32_t*>(&h);
}

#define LDSM4(r, a) \
    asm volatile("ldmatrix.sync.aligned.m8n8.x4.shared.b16 {%0,%1,%2,%3}, [%4];" \
                 : "=r"((r)[0]), "=r"((r)[1]), "=r"((r)[2]), "=r"((r)[3]) : "r"(a))
#define LDSM4T(r, a) \
    asm volatile("ldmatrix.sync.aligned.m8n8.x4.trans.shared.b16 {%0,%1,%2,%3}, [%4];" \
                 : "=r"((r)[0]), "=r"((r)[1]), "=r"((r)[2]), "=r"((r)[3]) : "r"(a))
#define MMA16816(d, a, b) \
    asm volatile("mma.sync.aligned.m16n8k16.row.col.f32.f16.f16.f32 " \
                 "{%0,%1,%2,%3}, {%4,%5,%6,%7}, {%8,%9}, {%0,%1,%2,%3};" \
                 : "+f"((d)[0]), "+f"((d)[1]), "+f"((d)[2]), "+f"((d)[3]) \
                 : "r"((a)[0]), "r"((a)[1]), "r"((a)[2]), "r"((a)[3]), \
                   "r"((b)[0]), "r"((b)[1]))
#define CP16(dst, src) \
    asm volatile("cp.async.ca.shared.global [%0], [%1], 16;" \
                 :: "r"(dst), "l"(src) : "memory")
#define CP_COMMIT() asm volatile("cp.async.commit_group;" ::: "memory")
#define CP_WAIT(n)  asm volatile("cp.async.wait_group %0;" :: "n"(n) : "memory")

// GEMM smem swizzle: 2 logical 32-elem rows per 128B line
__device__ __forceinline__ uint32_t swz(int m, int c) {
    return (uint32_t)((m >> 1) * 128 + (((((m & 1) << 2) | c) ^ ((m >> 1) & 7)) << 4));
}
// attention smem swizzle: 64-elem rows, 128B lines
__device__ __forceinline__ uint32_t sw128(int m, int u) {
    return (uint32_t)(m * 128 + ((u ^ (m & 7)) << 4));
}

// ---------------------------------------------------------------------------
// Fused fp32 -> fp16 convert pass: 3 inputs + 4 weights -> hi planes only
// ---------------------------------------------------------------------------
__global__ __launch_bounds__(256)
void cvt_all_kernel(const float4* __restrict__ q, const float4* __restrict__ k,
                    const float4* __restrict__ v,
                    const float4* __restrict__ wq, const float4* __restrict__ wk,
                    const float4* __restrict__ wv, const float4* __restrict__ wo,
                    uint2* __restrict__ ih, uint2* __restrict__ wh)
{
    const int NI = TOKENS * EMBED / 4;
    const int NW = EMBED * EMBED / 4;
    int i = blockIdx.x * 256 + threadIdx.x;

    float4 val;
    uint2* dst;
    if (i < 3 * NI) {
        int seg = i / NI;
        int off = i - seg * NI;
        val = *((seg == 0 ? q : seg == 1 ? k : v) + off);
        dst = ih + (size_t)seg * NI + off;
    } else {
        int j = i - 3 * NI;
        int seg = j / NW;
        int off = j - seg * NW;
        val = *((seg == 0 ? wq : seg == 1 ? wk : seg == 2 ? wv : wo) + off);
        dst = wh + (size_t)seg * NW + off;
    }
    uint2 Hv;
    Hv.x = cvt2h(val.x, val.y);
    Hv.y = cvt2h(val.z, val.w);
    *dst = Hv;
}

// ---------------------------------------------------------------------------
// fp16 1-term GEMM: C = Ah @ Wh^T + bias -> fp16 plane outputs.
// 128x128 CTA, BK=32, 8 warps (64x32), 3-stage cp.async, 2 CTAs/SM.
// stage: Ah 8K | Wh 8K = 16KB.
// ---------------------------------------------------------------------------
#define G1_STAGE 16384u
#define GEMM1_SMEM (3 * 16384)

__global__ __launch_bounds__(256, 2)
void gemm_f16x1_kernel(const __half* __restrict__ Ah_b, int strideAz,
                       const __half* __restrict__ Wh_b, int strideWz,
                       const float* __restrict__ b0, const float* __restrict__ b1,
                       const float* __restrict__ b2,
                       __half* __restrict__ H0, __half* __restrict__ H1,
                       __half* __restrict__ H2)
{
    extern __shared__ char sm[];
    const uint32_t sb = smem_u32(sm);
    const int tid  = threadIdx.x;
    const int wid  = tid >> 5;
    const int lane = tid & 31;

    const int z = blockIdx.z;
    const __half* Ah = Ah_b + (size_t)z * strideAz;
    const __half* Wh = Wh_b + (size_t)z * strideWz;
    const float* bias = (z == 0) ? b0 : (z == 1) ? b1 : b2;
    __half* Hi = (z == 0) ? H0 : (z == 1) ? H1 : H2;

    const int row0 = blockIdx.y * 128;
    const int col0 = blockIdx.x * 128;
    const int wm = (wid & 1) * 64;
    const int wn = (wid >> 1) * 32;

    const int lm = tid >> 1;
    const int lc = (tid & 1) * 2;
    const __half* gAh = Ah + (size_t)(row0 + lm) * EMBED + lc * 8;
    const __half* gWh = Wh + (size_t)(col0 + lm) * EMBED + lc * 8;
    const uint32_t s0 = swz(lm, lc);
    const uint32_t s1 = swz(lm, lc + 1);

    float acc[4][4][4];
#pragma unroll
    for (int i = 0; i < 4; i++)
#pragma unroll
        for (int j = 0; j < 4; j++)
#pragma unroll
            for (int q = 0; q < 4; q++) acc[i][j][q] = 0.0f;

    auto issue = [&](int ch) {
        const uint32_t st = sb + (uint32_t)(ch % 3) * G1_STAGE;
        const int ko = ch * 32;
        CP16(st         + s0, gAh + ko);
        CP16(st         + s1, gAh + ko + 8);
        CP16(st + 8192u + s0, gWh + ko);
        CP16(st + 8192u + s1, gWh + ko + 8);
    };

    issue(0); CP_COMMIT();
    issue(1); CP_COMMIT();

    const int mA  = wm + (lane & 7) + ((lane >> 3) & 1) * 8;
    const int cA  = (lane >> 4);
    const int nB4 = wn + (lane & 7) + ((lane >> 4) << 3);
    const int cB4 = ((lane >> 3) & 1);

    const int NCHUNK = EMBED / 32;
    for (int ch = 0; ch < NCHUNK; ch++) {
        if (ch + 1 < NCHUNK) { CP_WAIT(1); } else { CP_WAIT(0); }
        __syncthreads();
        if (ch + 2 < NCHUNK) { issue(ch + 2); CP_COMMIT(); }

        const uint32_t stb = sb + (uint32_t)(ch % 3) * G1_STAGE;
#pragma unroll
        for (int ks = 0; ks < 2; ks++) {
            uint32_t ah[4][4], bh[4][2];
            const int ca = ks * 2 + cA;
            const int cb = ks * 2 + cB4;
#pragma unroll
            for (int i = 0; i < 4; i++)
                LDSM4(ah[i], stb + swz(mA + i * 16, ca));
#pragma unroll
            for (int jj = 0; jj < 2; jj++) {
                uint32_t t[4];
                LDSM4(t, stb + 8192 + swz(nB4 + jj * 16, cb));
                bh[2 * jj][0] = t[0]; bh[2 * jj][1] = t[1];
                bh[2 * jj + 1][0] = t[2]; bh[2 * jj + 1][1] = t[3];
            }
#pragma unroll
            for (int i = 0; i < 4; i++)
#pragma unroll
                for (int j = 0; j < 4; j++)
                    MMA16816(acc[i][j], ah[i], bh[j]);
        }
    }

    const int mrow = row0 + wm + (lane >> 2);
    const int ncol = col0 + wn + (lane & 3) * 2;
#pragma unroll
    for (int i = 0; i < 4; i++)
#pragma unroll
        for (int j = 0; j < 4; j++) {
            const int r  = mrow + i * 16;
            const int cn = ncol + j * 8;
            const float bx = bias[cn], by = bias[cn + 1];
            *(uint32_t*)(Hi + (size_t)r       * EMBED + cn) =
                cvt2h(acc[i][j][0] + bx, acc[i][j][1] + by);
            *(uint32_t*)(Hi + (size_t)(r + 8) * EMBED + cn) =
                cvt2h(acc[i][j][2] + bx, acc[i][j][3] + by);
        }
}

// ---------------------------------------------------------------------------
// fp16 2-term GEMM: C = (Ah+Al) @ Wh^T + bias -> fp32 output.
// stage: Ah 8K | Al 8K | Wh 8K = 24KB.
// ---------------------------------------------------------------------------
#define G2_STAGE 24576u
#define GEMM2_SMEM (3 * 24576)

__global__ __launch_bounds__(256, 2)
void gemm_f16x2_kernel(const __half* __restrict__ Ah, const __half* __restrict__ Al,
                       const __half* __restrict__ Wh,
                       const float* __restrict__ bias,
                       float* __restrict__ Cf)
{
    extern __shared__ char sm[];
    const uint32_t sb = smem_u32(sm);
    const int tid  = threadIdx.x;
    const int wid  = tid >> 5;
    const int lane = tid & 31;

    const int row0 = blockIdx.y * 128;
    const int col0 = blockIdx.x * 128;
    const int wm = (wid & 1) * 64;
    const int wn = (wid >> 1) * 32;

    const int lm = tid >> 1;
    const int lc = (tid & 1) * 2;
    const __half* gAh = Ah + (size_t)(row0 + lm) * EMBED + lc * 8;
    const __half* gAl = Al + (size_t)(row0 + lm) * EMBED + lc * 8;
    const __half* gWh = Wh + (size_t)(col0 + lm) * EMBED + lc * 8;
    const uint32_t s0 = swz(lm, lc);
    const uint32_t s1 = swz(lm, lc + 1);

    float acc[4][4][4];
#pragma unroll
    for (int i = 0; i < 4; i++)
#pragma unroll
        for (int j = 0; j < 4; j++)
#pragma unroll
            for (int q = 0; q < 4; q++) acc[i][j][q] = 0.0f;

    auto issue = [&](int ch) {
        const uint32_t st = sb + (uint32_t)(ch % 3) * G2_STAGE;
        const int ko = ch * 32;
        CP16(st             + s0, gAh + ko);
        CP16(st             + s1, gAh + ko + 8);
        CP16(st +     8192u + s0, gAl + ko);
        CP16(st +     8192u + s1, gAl + ko + 8);
        CP16(st + 2 * 8192u + s0, gWh + ko);
        CP16(st + 2 * 8192u + s1, gWh + ko + 8);
    };

    issue(0); CP_COMMIT();
    issue(1); CP_COMMIT();

    const int mA  = wm + (lane & 7) + ((lane >> 3) & 1) * 8;
    const int cA  = (lane >> 4);
    const int nB4 = wn + (lane & 7) + ((lane >> 4) << 3);
    const int cB4 = ((lane >> 3) & 1);

    const int NCHUNK = EMBED / 32;
    for (int ch = 0; ch < NCHUNK; ch++) {
        if (ch + 1 < NCHUNK) { CP_WAIT(1); } else { CP_WAIT(0); }
        __syncthreads();
        if (ch + 2 < NCHUNK) { issue(ch + 2); CP_COMMIT(); }

        const uint32_t stb = sb + (uint32_t)(ch % 3) * G2_STAGE;
#pragma unroll
        for (int ks = 0; ks < 2; ks++) {
            uint32_t ah[4][4], al[4][4], bh[4][2];
            const int ca = ks * 2 + cA;
            const int cb = ks * 2 + cB4;
#pragma unroll
            for (int i = 0; i < 4; i++) {
                LDSM4(ah[i], stb        + swz(mA + i * 16, ca));
                LDSM4(al[i], stb + 8192 + swz(mA + i * 16, ca));
            }
#pragma unroll
            for (int jj = 0; jj < 2; jj++) {
                uint32_t t[4];
                LDSM4(t, stb + 2 * 8192 + swz(nB4 + jj * 16, cb));
                bh[2 * jj][0] = t[0]; bh[2 * jj][1] = t[1];
                bh[2 * jj + 1][0] = t[2]; bh[2 * jj + 1][1] = t[3];
            }
#pragma unroll
            for (int i = 0; i < 4; i++)
#pragma unroll
                for (int j = 0; j < 4; j++) {
                    MMA16816(acc[i][j], ah[i], bh[j]);
                    MMA16816(acc[i][j], al[i], bh[j]);
                }
        }
    }

    const int mrow = row0 + wm + (lane >> 2);
    const int ncol = col0 + wn + (lane & 3) * 2;
#pragma unroll
    for (int i = 0; i < 4; i++)
#pragma unroll
        for (int j = 0; j < 4; j++) {
            const int r  = mrow + i * 16;
            const int cn = ncol + j * 8;
            const float bx = bias[cn], by = bias[cn + 1];
            float2 v0 = make_float2(acc[i][j][0] + bx, acc[i][j][1] + by);
            float2 v1 = make_float2(acc[i][j][2] + bx, acc[i][j][3] + by);
            *(float2*)(Cf + (size_t)r       * EMBED + cn) = v0;
            *(float2*)(Cf + (size_t)(r + 8) * EMBED + cn) = v1;
        }
}

// ---------------------------------------------------------------------------
// fp16 tensor-core flash attention (R12-proven):
//   S = Qh Kh^T (1-term); O += (Ph+Pl) Vh (2-term).
// K-tile 64, 2-stage cp.async. stage: Kh 8K | Vh 8K | mask 256B.
// ---------------------------------------------------------------------------
#define KT 64
#define ATT_STAGE (2 * 8192 + 256)
#define ATT_SMEM  (16384 + 2 * ATT_STAGE)   // 49664 B

__global__ __launch_bounds__(256, 2)
void attention_tc_kernel(const __half* __restrict__ Qh,
                         const __half* __restrict__ Kh,
                         const __half* __restrict__ Vh,
                         const int* __restrict__ mask,
                         __half* __restrict__ Ohi,
                         __half* __restrict__ Olo)
{
    extern __shared__ char sm[];
    const uint32_t sb = smem_u32(sm);
    const uint32_t oQ = 0, oStage = 16384;
    const int tid  = threadIdx.x;
    const int lane = tid & 31;
    const int w    = tid >> 5;
    const int qt   = blockIdx.x;
    const int h    = blockIdx.y;
    const int b    = blockIdx.z;
    const int colh = h * HEAD_DIM;
    const size_t base = (size_t)b * SEQ * EMBED;
    const float CEXP = 1.4426950408889634f / 32.0f;

    auto issueKV = [&](int kt) {
        const uint32_t ksb = sb + oStage + (uint32_t)(kt & 1) * ATT_STAGE;
#pragma unroll
        for (int it = 0; it < 2; it++) {
            int idx = tid + it * 256;
            int r = idx >> 3, u = idx & 7;
            size_t g = base + (size_t)(kt * KT + r) * EMBED + colh + u * 8;
            uint32_t so = sw128(r, u);
            CP16(ksb         + so, Kh + g);
            CP16(ksb + 8192u + so, Vh + g);
        }
        if (tid < 16)
            CP16(ksb + 2 * 8192u + (uint32_t)tid * 16u,
                 mask + b * SEQ + kt * KT + tid * 4);
    };

    issueKV(0); CP_COMMIT();

#pragma unroll
    for (int it = 0; it < 4; it++) {
        int idx = tid + it * 256;
        int r = idx >> 3, u = idx & 7;
        size_t g = base + (size_t)(qt * 128 + r) * EMBED + colh + u * 8;
        *(uint4*)(sm + oQ + sw128(r, u)) = *(const uint4*)(Qh + g);
    }

    const int q0 = w * 16;
    float o[8][4];
#pragma unroll
    for (int j = 0; j < 8; j++)
#pragma unroll
        for (int q = 0; q < 4; q++) o[j][q] = 0.0f;
    const float NEG_INF = __int_as_float(0xff800000);
    float mr0 = NEG_INF, mr1 = NEG_INF, lr0 = 0.0f, lr1 = 0.0f;

    const uint32_t rowA = (uint32_t)(q0 + (lane & 15));
    const uint32_t uA   = (uint32_t)(lane >> 4);
    const uint32_t rowB = (uint32_t)((lane & 7) + ((lane >> 4) << 3));
    const uint32_t uB   = (uint32_t)((lane >> 3) & 1);
    const uint32_t rowV = (uint32_t)((lane & 7) + (((lane >> 3) & 1) << 3));
    const uint32_t uV   = (uint32_t)(lane >> 4);

    const int NITER = SEQ / KT;
    for (int kt = 0; kt < NITER; kt++) {
        if (kt + 1 < NITER) { issueKV(kt + 1); CP_COMMIT(); CP_WAIT(1); }
        else                { CP_WAIT(0); }
        __syncthreads();

        const uint32_t stg = sb + oStage + (uint32_t)(kt & 1) * ATT_STAGE;
        const uint32_t oKh = stg, oVh = stg + 8192;
        const int* msk = (const int*)(sm + (oStage + (uint32_t)(kt & 1) * ATT_STAGE
                                            + 2 * 8192));

        // ---- S = Qh Kh^T (1-term) ----
        float s[8][4];
#pragma unroll
        for (int j = 0; j < 8; j++)
#pragma unroll
            for (int q = 0; q < 4; q++) s[j][q] = 0.0f;

#pragma unroll
        for (int ks = 0; ks < 4; ks++) {
            uint32_t ah[4];
            const uint32_t ua = uA + ks * 2;
            const uint32_t aoff = rowA * 128 + ((ua ^ (rowA & 7)) << 4);
            LDSM4(ah, sb + oQ + aoff);
#pragma unroll
            for (int np = 0; np < 4; np++) {
                const uint32_t rb = rowB + np * 16;
                const uint32_t ub = uB + ks * 2;
                const uint32_t boff = rb * 128 + ((ub ^ (rb & 7)) << 4);
                uint32_t kh4[4];
                LDSM4(kh4, oKh + boff);
                MMA16816(s[2 * np],     ah, kh4);
                MMA16816(s[2 * np + 1], ah, kh4 + 2);
            }
        }

        // ---- mask + online softmax ----
        const int cb2 = (lane & 3) * 2;
        float mx0 = NEG_INF, mx1 = NEG_INF;
#pragma unroll
        for (int j = 0; j < 8; j++) {
            const int col = j * 8 + cb2;
            const int m0v = msk[col], m1v = msk[col + 1];
            if (!m0v) { s[j][0] = -1e20f; s[j][2] = -1e20f; }
            if (!m1v) { s[j][1] = -1e20f; s[j][3] = -1e20f; }
            mx0 = fmaxf(mx0, fmaxf(s[j][0], s[j][1]));
            mx1 = fmaxf(mx1, fmaxf(s[j][2], s[j][3]));
        }
        mx0 = fmaxf(mx0, __shfl_xor_sync(0xffffffffu, mx0, 1));
        mx0 = fmaxf(mx0, __shfl_xor_sync(0xffffffffu, mx0, 2));
        mx1 = fmaxf(mx1, __shfl_xor_sync(0xffffffffu, mx1, 1));
        mx1 = fmaxf(mx1, __shfl_xor_sync(0xffffffffu, mx1, 2));

        const float mn0 = fmaxf(mr0, mx0);
        const float mn1 = fmaxf(mr1, mx1);
        const float c0 = fast_exp2((mr0 - mn0) * CEXP);
        const float c1 = fast_exp2((mr1 - mn1) * CEXP);
        mr0 = mn0; mr1 = mn1;

        float sum0 = 0.0f, sum1 = 0.0f;
#pragma unroll
        for (int j = 0; j < 8; j++) {
            s[j][0] = fast_exp2((s[j][0] - mn0) * CEXP);
            s[j][1] = fast_exp2((s[j][1] - mn0) * CEXP);
            s[j][2] = fast_exp2((s[j][2] - mn1) * CEXP);
            s[j][3] = fast_exp2((s[j][3] - mn1) * CEXP);
            sum0 += s[j][0] + s[j][1];
            sum1 += s[j][2] + s[j][3];
        }
        sum0 += __shfl_xor_sync(0xffffffffu, sum0, 1);
        sum0 += __shfl_xor_sync(0xffffffffu, sum0, 2);
        sum1 += __shfl_xor_sync(0xffffffffu, sum1, 1);
        sum1 += __shfl_xor_sync(0xffffffffu, sum1, 2);
        lr0 = lr0 * c0 + sum0;
        lr1 = lr1 * c1 + sum1;
#pragma unroll
        for (int jd = 0; jd < 8; jd++) {
            o[jd][0] *= c0; o[jd][1] *= c0;
            o[jd][2] *= c1; o[jd][3] *= c1;
        }

        // ---- O += (Ph+Pl) Vh (2-term) ----
#pragma unroll
        for (int kk = 0; kk < 4; kk++) {
            uint32_t ph[4], pl[4];
            ph[0] = split2h(s[2 * kk][0],     s[2 * kk][1],     pl[0]);
            ph[1] = split2h(s[2 * kk][2],     s[2 * kk][3],     pl[1]);
            ph[2] = split2h(s[2 * kk + 1][0], s[2 * kk + 1][1], pl[2]);
            ph[3] = split2h(s[2 * kk + 1][2], s[2 * kk + 1][3], pl[3]);
            const uint32_t k0 = kk * 16;
#pragma unroll
            for (int jdp = 0; jdp < 4; jdp++) {
                const uint32_t rv = k0 + rowV;
                const uint32_t uv = jdp * 2 + uV;
                const uint32_t voff = rv * 128 + ((uv ^ (rv & 7)) << 4);
                uint32_t bh4[4];
                LDSM4T(bh4, oVh + voff);
                MMA16816(o[2 * jdp],     ph, bh4);
                MMA16816(o[2 * jdp],     pl, bh4);
                MMA16816(o[2 * jdp + 1], ph, bh4 + 2);
                MMA16816(o[2 * jdp + 1], pl, bh4 + 2);
            }
        }
        __syncthreads();
    }

    // ---- epilogue: normalize, split fp16 hi/lo for the out-projection ----
    const float inv0 = 1.0f / lr0;
    const float inv1 = 1.0f / lr1;
    const int r0g = qt * 128 + q0 + (lane >> 2);
    const int cbe = (lane & 3) * 2;
#pragma unroll
    for (int jd = 0; jd < 8; jd++) {
        const int cn = colh + jd * 8 + cbe;
        uint32_t l0v, l1v;
        uint32_t h0v = split2h(o[jd][0] * inv0, o[jd][1] * inv0, l0v);
        uint32_t h1v = split2h(o[jd][2] * inv1, o[jd][3] * inv1, l1v);
        size_t i0 = base + (size_t)r0g * EMBED + cn;
        size_t i1 = base + (size_t)(r0g + 8) * EMBED + cn;
        *(uint32_t*)(Ohi + i0) = h0v;
        *(uint32_t*)(Olo + i0) = l0v;
        *(uint32_t*)(Ohi + i1) = h1v;
        *(uint32_t*)(Olo + i1) = l1v;
    }
}

// ---------------------------------------------------------------------------
// Launch
// ---------------------------------------------------------------------------
extern "C" void kernel_launch(void* const* d_in, const int* in_sizes, int n_in,
                              void* d_out, int out_size)
{
    const float* query = (const float*)d_in[0];
    const float* key   = (const float*)d_in[1];
    const float* value = (const float*)d_in[2];
    const int*   mask  = (const int*)  d_in[3];
    const float* Wq    = (const float*)d_in[4];
    const float* bq    = (const float*)d_in[5];
    const float* Wk    = (const float*)d_in[6];
    const float* bk    = (const float*)d_in[7];
    const float* Wv    = (const float*)d_in[8];
    const float* bv    = (const float*)d_in[9];
    const float* Wo    = (const float*)d_in[10];
    const float* bo    = (const float*)d_in[11];
    float* out = (float*)d_out;

    __half *ih, *wh, *qh, *kh, *vh, *aoh, *aol;
    cudaGetSymbolAddress((void**)&ih,  g_in_h);
    cudaGetSymbolAddress((void**)&wh,  g_w_h);
    cudaGetSymbolAddress((void**)&qh,  g_qh);
    cudaGetSymbolAddress((void**)&kh,  g_kh);
    cudaGetSymbolAddress((void**)&vh,  g_vh);
    cudaGetSymbolAddress((void**)&aoh, g_ao_hi);
    cudaGetSymbolAddress((void**)&aol, g_ao_lo);

    cudaFuncSetAttribute(gemm_f16x1_kernel,
                         cudaFuncAttributeMaxDynamicSharedMemorySize, GEMM1_SMEM);
    cudaFuncSetAttribute(gemm_f16x2_kernel,
                         cudaFuncAttributeMaxDynamicSharedMemorySize, GEMM2_SMEM);
    cudaFuncSetAttribute(attention_tc_kernel,
                         cudaFuncAttributeMaxDynamicSharedMemorySize, ATT_SMEM);

    // One fused convert pass: inputs + weights -> fp16 hi planes
    const int NI = TOKENS * EMBED / 4;
    const int NW = EMBED * EMBED / 4;
    cvt_all_kernel<<<(3 * NI + 4 * NW) / 256, 256>>>(
        (const float4*)query, (const float4*)key, (const float4*)value,
        (const float4*)Wq, (const float4*)Wk, (const float4*)Wv, (const float4*)Wo,
        (uint2*)ih, (uint2*)wh);

    // QKV projections: 1-term fp16 GEMM -> fp16 planes
    gemm_f16x1_kernel<<<dim3(EMBED / 128, TOKENS / 128, 3), 256, GEMM1_SMEM>>>(
        ih, TOKENS * EMBED, wh, EMBED * EMBED,
        bq, bk, bv, qh, kh, vh);

    // fp16 flash attention -> hi/lo output planes
    attention_tc_kernel<<<dim3(SEQ / 128, HEADS, BATCH), 256, ATT_SMEM>>>(
        qh, kh, vh, mask, aoh, aol);

    // Output projection: 2-term fp16 GEMM -> fp32
    gemm_f16x2_kernel<<<dim3(EMBED / 128, TOKENS / 128, 1), 256, GEMM2_SMEM>>>(
        aoh, aol, wh + (size_t)3 * EMBED * EMBED, bo, out);
}

// round 17
// speedup vs baseline: 2.9640x; 1.0852x over previous
#include <cuda_runtime.h>
#include <cuda_fp16.h>
#include <cstdint>
#include <math.h>

#define EMBED    1024
#define HEADS    16
#define HEAD_DIM 64
#define BATCH    2
#define SEQ      2048
#define TOKENS   (BATCH * SEQ)

// ---------------------------------------------------------------------------
// Scratch (device globals)
// ---------------------------------------------------------------------------
__device__ __half g_in_h [3 * TOKENS * EMBED];
__device__ __half g_w_h  [4 * EMBED * EMBED];
__device__ __half g_qh[TOKENS * EMBED];
__device__ __half g_kh[TOKENS * EMBED];
__device__ __half g_vh[TOKENS * EMBED];
__device__ __half g_ao_hi[TOKENS * EMBED];
__device__ __half g_ao_lo[TOKENS * EMBED];

__device__ __forceinline__ uint32_t smem_u32(const void* p) {
    uint32_t a;
    asm("{ .reg .u64 t; cvta.to.shared.u64 t, %1; cvt.u32.u64 %0, t; }"
        : "=r"(a) : "l"(p));
    return a;
}
__device__ __forceinline__ float fast_exp2(float x) {
    float y;
    asm("ex2.approx.f32 %0, %1;" : "=f"(y) : "f"(x));
    return y;
}
// fp16 hi/lo split: hi+lo reproduces the fp32 value to ~2^-23
__device__ __forceinline__ uint32_t split2h(float a, float b, uint32_t& lo) {
    __half2 h = __floats2half2_rn(a, b);
    __half2 l = __floats2half2_rn(a - __half2float(__low2half(h)),
                                  b - __half2float(__high2half(h)));
    lo = *reinterpret_cast<uint32_t*>(&l);
    return *reinterpret_cast<uint32_t*>(&h);
}
__device__ __forceinline__ uint32_t cvt2h(float a, float b) {
    __half2 h = __floats2half2_rn(a, b);
    return *reinterpret_cast<uint32_t*>(&h);
}

#define LDSM4(r, a) \
    asm volatile("ldmatrix.sync.aligned.m8n8.x4.shared.b16 {%0,%1,%2,%3}, [%4];" \
                 : "=r"((r)[0]), "=r"((r)[1]), "=r"((r)[2]), "=r"((r)[3]) : "r"(a))
#define LDSM4T(r, a) \
    asm volatile("ldmatrix.sync.aligned.m8n8.x4.trans.shared.b16 {%0,%1,%2,%3}, [%4];" \
                 : "=r"((r)[0]), "=r"((r)[1]), "=r"((r)[2]), "=r"((r)[3]) : "r"(a))
#define MMA16816(d, a, b) \
    asm volatile("mma.sync.aligned.m16n8k16.row.col.f32.f16.f16.f32 " \
                 "{%0,%1,%2,%3}, {%4,%5,%6,%7}, {%8,%9}, {%0,%1,%2,%3};" \
                 : "+f"((d)[0]), "+f"((d)[1]), "+f"((d)[2]), "+f"((d)[3]) \
                 : "r"((a)[0]), "r"((a)[1]), "r"((a)[2]), "r"((a)[3]), \
                   "r"((b)[0]), "r"((b)[1]))
#define CP16(dst, src) \
    asm volatile("cp.async.ca.shared.global [%0], [%1], 16;" \
                 :: "r"(dst), "l"(src) : "memory")
#define CP_COMMIT() asm volatile("cp.async.commit_group;" ::: "memory")
#define CP_WAIT(n)  asm volatile("cp.async.wait_group %0;" :: "n"(n) : "memory")

// GEMM smem swizzle: 2 logical 32-elem rows per 128B line
__device__ __forceinline__ uint32_t swz(int m, int c) {
    return (uint32_t)((m >> 1) * 128 + (((((m & 1) << 2) | c) ^ ((m >> 1) & 7)) << 4));
}
// attention smem swizzle: 64-elem rows, 128B lines
__device__ __forceinline__ uint32_t sw128(int m, int u) {
    return (uint32_t)(m * 128 + ((u ^ (m & 7)) << 4));
}

// ---------------------------------------------------------------------------
// Fused fp32 -> fp16 convert pass: 3 inputs + 4 weights -> hi planes only
// ---------------------------------------------------------------------------
__global__ __launch_bounds__(256)
void cvt_all_kernel(const float4* __restrict__ q, const float4* __restrict__ k,
                    const float4* __restrict__ v,
                    const float4* __restrict__ wq, const float4* __restrict__ wk,
                    const float4* __restrict__ wv, const float4* __restrict__ wo,
                    uint2* __restrict__ ih, uint2* __restrict__ wh)
{
    const int NI = TOKENS * EMBED / 4;
    const int NW = EMBED * EMBED / 4;
    int i = blockIdx.x * 256 + threadIdx.x;

    float4 val;
    uint2* dst;
    if (i < 3 * NI) {
        int seg = i / NI;
        int off = i - seg * NI;
        val = *((seg == 0 ? q : seg == 1 ? k : v) + off);
        dst = ih + (size_t)seg * NI + off;
    } else {
        int j = i - 3 * NI;
        int seg = j / NW;
        int off = j - seg * NW;
        val = *((seg == 0 ? wq : seg == 1 ? wk : seg == 2 ? wv : wo) + off);
        dst = wh + (size_t)seg * NW + off;
    }
    uint2 Hv;
    Hv.x = cvt2h(val.x, val.y);
    Hv.y = cvt2h(val.z, val.w);
    *dst = Hv;
}

// ---------------------------------------------------------------------------
// fp16 1-term GEMM: C = Ah @ Wh^T + bias -> fp16 plane outputs.
// 128x128 CTA, BK=32, 8 warps (64x32), 3-stage cp.async, 2 CTAs/SM.
// stage: Ah 8K | Wh 8K = 16KB.
// ---------------------------------------------------------------------------
#define G1_STAGE 16384u
#define GEMM1_SMEM (3 * 16384)

__global__ __launch_bounds__(256, 2)
void gemm_f16x1_kernel(const __half* __restrict__ Ah_b, int strideAz,
                       const __half* __restrict__ Wh_b, int strideWz,
                       const float* __restrict__ b0, const float* __restrict__ b1,
                       const float* __restrict__ b2,
                       __half* __restrict__ H0, __half* __restrict__ H1,
                       __half* __restrict__ H2)
{
    extern __shared__ char sm[];
    const uint32_t sb = smem_u32(sm);
    const int tid  = threadIdx.x;
    const int wid  = tid >> 5;
    const int lane = tid & 31;

    const int z = blockIdx.z;
    const __half* Ah = Ah_b + (size_t)z * strideAz;
    const __half* Wh = Wh_b + (size_t)z * strideWz;
    const float* bias = (z == 0) ? b0 : (z == 1) ? b1 : b2;
    __half* Hi = (z == 0) ? H0 : (z == 1) ? H1 : H2;

    const int row0 = blockIdx.y * 128;
    const int col0 = blockIdx.x * 128;
    const int wm = (wid & 1) * 64;
    const int wn = (wid >> 1) * 32;

    const int lm = tid >> 1;
    const int lc = (tid & 1) * 2;
    const __half* gAh = Ah + (size_t)(row0 + lm) * EMBED + lc * 8;
    const __half* gWh = Wh + (size_t)(col0 + lm) * EMBED + lc * 8;
    const uint32_t s0 = swz(lm, lc);
    const uint32_t s1 = swz(lm, lc + 1);

    float acc[4][4][4];
#pragma unroll
    for (int i = 0; i < 4; i++)
#pragma unroll
        for (int j = 0; j < 4; j++)
#pragma unroll
            for (int q = 0; q < 4; q++) acc[i][j][q] = 0.0f;

    auto issue = [&](int ch) {
        const uint32_t st = sb + (uint32_t)(ch % 3) * G1_STAGE;
        const int ko = ch * 32;
        CP16(st         + s0, gAh + ko);
        CP16(st         + s1, gAh + ko + 8);
        CP16(st + 8192u + s0, gWh + ko);
        CP16(st + 8192u + s1, gWh + ko + 8);
    };

    issue(0); CP_COMMIT();
    issue(1); CP_COMMIT();

    const int mA  = wm + (lane & 7) + ((lane >> 3) & 1) * 8;
    const int cA  = (lane >> 4);
    const int nB4 = wn + (lane & 7) + ((lane >> 4) << 3);
    const int cB4 = ((lane >> 3) & 1);

    const int NCHUNK = EMBED / 32;
    for (int ch = 0; ch < NCHUNK; ch++) {
        if (ch + 1 < NCHUNK) { CP_WAIT(1); } else { CP_WAIT(0); }
        __syncthreads();
        if (ch + 2 < NCHUNK) { issue(ch + 2); CP_COMMIT(); }

        const uint32_t stb = sb + (uint32_t)(ch % 3) * G1_STAGE;
#pragma unroll
        for (int ks = 0; ks < 2; ks++) {
            uint32_t ah[4][4], bh[4][2];
            const int ca = ks * 2 + cA;
            const int cb = ks * 2 + cB4;
#pragma unroll
            for (int i = 0; i < 4; i++)
                LDSM4(ah[i], stb + swz(mA + i * 16, ca));
#pragma unroll
            for (int jj = 0; jj < 2; jj++) {
                uint32_t t[4];
                LDSM4(t, stb + 8192 + swz(nB4 + jj * 16, cb));
                bh[2 * jj][0] = t[0]; bh[2 * jj][1] = t[1];
                bh[2 * jj + 1][0] = t[2]; bh[2 * jj + 1][1] = t[3];
            }
#pragma unroll
            for (int i = 0; i < 4; i++)
#pragma unroll
                for (int j = 0; j < 4; j++)
                    MMA16816(acc[i][j], ah[i], bh[j]);
        }
    }

    const int mrow = row0 + wm + (lane >> 2);
    const int ncol = col0 + wn + (lane & 3) * 2;
#pragma unroll
    for (int i = 0; i < 4; i++)
#pragma unroll
        for (int j = 0; j < 4; j++) {
            const int r  = mrow + i * 16;
            const int cn = ncol + j * 8;
            const float bx = bias[cn], by = bias[cn + 1];
            *(uint32_t*)(Hi + (size_t)r       * EMBED + cn) =
                cvt2h(acc[i][j][0] + bx, acc[i][j][1] + by);
            *(uint32_t*)(Hi + (size_t)(r + 8) * EMBED + cn) =
                cvt2h(acc[i][j][2] + bx, acc[i][j][3] + by);
        }
}

// ---------------------------------------------------------------------------
// fp16 2-term GEMM: C = (Ah+Al) @ Wh^T + bias -> fp32 output.
// stage: Ah 8K | Al 8K | Wh 8K = 24KB.
// ---------------------------------------------------------------------------
#define G2_STAGE 24576u
#define GEMM2_SMEM (3 * 24576)

__global__ __launch_bounds__(256, 2)
void gemm_f16x2_kernel(const __half* __restrict__ Ah, const __half* __restrict__ Al,
                       const __half* __restrict__ Wh,
                       const float* __restrict__ bias,
                       float* __restrict__ Cf)
{
    extern __shared__ char sm[];
    const uint32_t sb = smem_u32(sm);
    const int tid  = threadIdx.x;
    const int wid  = tid >> 5;
    const int lane = tid & 31;

    const int row0 = blockIdx.y * 128;
    const int col0 = blockIdx.x * 128;
    const int wm = (wid & 1) * 64;
    const int wn = (wid >> 1) * 32;

    const int lm = tid >> 1;
    const int lc = (tid & 1) * 2;
    const __half* gAh = Ah + (size_t)(row0 + lm) * EMBED + lc * 8;
    const __half* gAl = Al + (size_t)(row0 + lm) * EMBED + lc * 8;
    const __half* gWh = Wh + (size_t)(col0 + lm) * EMBED + lc * 8;
    const uint32_t s0 = swz(lm, lc);
    const uint32_t s1 = swz(lm, lc + 1);

    float acc[4][4][4];
#pragma unroll
    for (int i = 0; i < 4; i++)
#pragma unroll
        for (int j = 0; j < 4; j++)
#pragma unroll
            for (int q = 0; q < 4; q++) acc[i][j][q] = 0.0f;

    auto issue = [&](int ch) {
        const uint32_t st = sb + (uint32_t)(ch % 3) * G2_STAGE;
        const int ko = ch * 32;
        CP16(st             + s0, gAh + ko);
        CP16(st             + s1, gAh + ko + 8);
        CP16(st +     8192u + s0, gAl + ko);
        CP16(st +     8192u + s1, gAl + ko + 8);
        CP16(st + 2 * 8192u + s0, gWh + ko);
        CP16(st + 2 * 8192u + s1, gWh + ko + 8);
    };

    issue(0); CP_COMMIT();
    issue(1); CP_COMMIT();

    const int mA  = wm + (lane & 7) + ((lane >> 3) & 1) * 8;
    const int cA  = (lane >> 4);
    const int nB4 = wn + (lane & 7) + ((lane >> 4) << 3);
    const int cB4 = ((lane >> 3) & 1);

    const int NCHUNK = EMBED / 32;
    for (int ch = 0; ch < NCHUNK; ch++) {
        if (ch + 1 < NCHUNK) { CP_WAIT(1); } else { CP_WAIT(0); }
        __syncthreads();
        if (ch + 2 < NCHUNK) { issue(ch + 2); CP_COMMIT(); }

        const uint32_t stb = sb + (uint32_t)(ch % 3) * G2_STAGE;
#pragma unroll
        for (int ks = 0; ks < 2; ks++) {
            uint32_t ah[4][4], al[4][4], bh[4][2];
            const int ca = ks * 2 + cA;
            const int cb = ks * 2 + cB4;
#pragma unroll
            for (int i = 0; i < 4; i++) {
                LDSM4(ah[i], stb        + swz(mA + i * 16, ca));
                LDSM4(al[i], stb + 8192 + swz(mA + i * 16, ca));
            }
#pragma unroll
            for (int jj = 0; jj < 2; jj++) {
                uint32_t t[4];
                LDSM4(t, stb + 2 * 8192 + swz(nB4 + jj * 16, cb));
                bh[2 * jj][0] = t[0]; bh[2 * jj][1] = t[1];
                bh[2 * jj + 1][0] = t[2]; bh[2 * jj + 1][1] = t[3];
            }
#pragma unroll
            for (int i = 0; i < 4; i++)
#pragma unroll
                for (int j = 0; j < 4; j++) {
                    MMA16816(acc[i][j], ah[i], bh[j]);
                    MMA16816(acc[i][j], al[i], bh[j]);
                }
        }
    }

    const int mrow = row0 + wm + (lane >> 2);
    const int ncol = col0 + wn + (lane & 3) * 2;
#pragma unroll
    for (int i = 0; i < 4; i++)
#pragma unroll
        for (int j = 0; j < 4; j++) {
            const int r  = mrow + i * 16;
            const int cn = ncol + j * 8;
            const float bx = bias[cn], by = bias[cn + 1];
            float2 v0 = make_float2(acc[i][j][0] + bx, acc[i][j][1] + by);
            float2 v1 = make_float2(acc[i][j][2] + bx, acc[i][j][3] + by);
            *(float2*)(Cf + (size_t)r       * EMBED + cn) = v0;
            *(float2*)(Cf + (size_t)(r + 8) * EMBED + cn) = v1;
        }
}

// ---------------------------------------------------------------------------
// fp16 tensor-core flash attention:
//   S = Qh Kh^T (1-term); O += Ph Vh (1-term; P is a convex-weight matrix,
//   fp16 truncation error ~2^-12 relative, partially cancelling).
// K-tile 64, 2-stage cp.async. stage: Kh 8K | Vh 8K | mask 256B.
// ---------------------------------------------------------------------------
#define KT 64
#define ATT_STAGE (2 * 8192 + 256)
#define ATT_SMEM  (16384 + 2 * ATT_STAGE)   // 49664 B

__global__ __launch_bounds__(256, 2)
void attention_tc_kernel(const __half* __restrict__ Qh,
                         const __half* __restrict__ Kh,
                         const __half* __restrict__ Vh,
                         const int* __restrict__ mask,
                         __half* __restrict__ Ohi,
                         __half* __restrict__ Olo)
{
    extern __shared__ char sm[];
    const uint32_t sb = smem_u32(sm);
    const uint32_t oQ = 0, oStage = 16384;
    const int tid  = threadIdx.x;
    const int lane = tid & 31;
    const int w    = tid >> 5;
    const int qt   = blockIdx.x;
    const int h    = blockIdx.y;
    const int b    = blockIdx.z;
    const int colh = h * HEAD_DIM;
    const size_t base = (size_t)b * SEQ * EMBED;
    const float CEXP = 1.4426950408889634f / 32.0f;

    auto issueKV = [&](int kt) {
        const uint32_t ksb = sb + oStage + (uint32_t)(kt & 1) * ATT_STAGE;
#pragma unroll
        for (int it = 0; it < 2; it++) {
            int idx = tid + it * 256;
            int r = idx >> 3, u = idx & 7;
            size_t g = base + (size_t)(kt * KT + r) * EMBED + colh + u * 8;
            uint32_t so = sw128(r, u);
            CP16(ksb         + so, Kh + g);
            CP16(ksb + 8192u + so, Vh + g);
        }
        if (tid < 16)
            CP16(ksb + 2 * 8192u + (uint32_t)tid * 16u,
                 mask + b * SEQ + kt * KT + tid * 4);
    };

    issueKV(0); CP_COMMIT();

    // Load Q tile (hi plane only)
#pragma unroll
    for (int it = 0; it < 4; it++) {
        int idx = tid + it * 256;
        int r = idx >> 3, u = idx & 7;
        size_t g = base + (size_t)(qt * 128 + r) * EMBED + colh + u * 8;
        *(uint4*)(sm + oQ + sw128(r, u)) = *(const uint4*)(Qh + g);
    }

    const int q0 = w * 16;
    float o[8][4];
#pragma unroll
    for (int j = 0; j < 8; j++)
#pragma unroll
        for (int q = 0; q < 4; q++) o[j][q] = 0.0f;
    const float NEG_INF = __int_as_float(0xff800000);
    float mr0 = NEG_INF, mr1 = NEG_INF, lr0 = 0.0f, lr1 = 0.0f;

    const uint32_t rowA = (uint32_t)(q0 + (lane & 15));
    const uint32_t uA   = (uint32_t)(lane >> 4);
    const uint32_t rowB = (uint32_t)((lane & 7) + ((lane >> 4) << 3));
    const uint32_t uB   = (uint32_t)((lane >> 3) & 1);
    const uint32_t rowV = (uint32_t)((lane & 7) + (((lane >> 3) & 1) << 3));
    const uint32_t uV   = (uint32_t)(lane >> 4);

    const int NITER = SEQ / KT;
    for (int kt = 0; kt < NITER; kt++) {
        if (kt + 1 < NITER) { issueKV(kt + 1); CP_COMMIT(); CP_WAIT(1); }
        else                { CP_WAIT(0); }
        __syncthreads();

        const uint32_t stg = sb + oStage + (uint32_t)(kt & 1) * ATT_STAGE;
        const uint32_t oKh = stg, oVh = stg + 8192;
        const int* msk = (const int*)(sm + (oStage + (uint32_t)(kt & 1) * ATT_STAGE
                                            + 2 * 8192));

        // ---- S = Qh Kh^T (1-term) ----
        float s[8][4];
#pragma unroll
        for (int j = 0; j < 8; j++)
#pragma unroll
            for (int q = 0; q < 4; q++) s[j][q] = 0.0f;

#pragma unroll
        for (int ks = 0; ks < 4; ks++) {
            uint32_t ah[4];
            const uint32_t ua = uA + ks * 2;
            const uint32_t aoff = rowA * 128 + ((ua ^ (rowA & 7)) << 4);
            LDSM4(ah, sb + oQ + aoff);
#pragma unroll
            for (int np = 0; np < 4; np++) {
                const uint32_t rb = rowB + np * 16;
                const uint32_t ub = uB + ks * 2;
                const uint32_t boff = rb * 128 + ((ub ^ (rb & 7)) << 4);
                uint32_t kh4[4];
                LDSM4(kh4, oKh + boff);
                MMA16816(s[2 * np],     ah, kh4);
                MMA16816(s[2 * np + 1], ah, kh4 + 2);
            }
        }

        // ---- mask + online softmax ----
        const int cb2 = (lane & 3) * 2;
        float mx0 = NEG_INF, mx1 = NEG_INF;
#pragma unroll
        for (int j = 0; j < 8; j++) {
            const int col = j * 8 + cb2;
            const int m0v = msk[col], m1v = msk[col + 1];
            if (!m0v) { s[j][0] = -1e20f; s[j][2] = -1e20f; }
            if (!m1v) { s[j][1] = -1e20f; s[j][3] = -1e20f; }
            mx0 = fmaxf(mx0, fmaxf(s[j][0], s[j][1]));
            mx1 = fmaxf(mx1, fmaxf(s[j][2], s[j][3]));
        }
        mx0 = fmaxf(mx0, __shfl_xor_sync(0xffffffffu, mx0, 1));
        mx0 = fmaxf(mx0, __shfl_xor_sync(0xffffffffu, mx0, 2));
        mx1 = fmaxf(mx1, __shfl_xor_sync(0xffffffffu, mx1, 1));
        mx1 = fmaxf(mx1, __shfl_xor_sync(0xffffffffu, mx1, 2));

        const float mn0 = fmaxf(mr0, mx0);
        const float mn1 = fmaxf(mr1, mx1);
        const float c0 = fast_exp2((mr0 - mn0) * CEXP);
        const float c1 = fast_exp2((mr1 - mn1) * CEXP);
        mr0 = mn0; mr1 = mn1;

        float sum0 = 0.0f, sum1 = 0.0f;
#pragma unroll
        for (int j = 0; j < 8; j++) {
            s[j][0] = fast_exp2((s[j][0] - mn0) * CEXP);
            s[j][1] = fast_exp2((s[j][1] - mn0) * CEXP);
            s[j][2] = fast_exp2((s[j][2] - mn1) * CEXP);
            s[j][3] = fast_exp2((s[j][3] - mn1) * CEXP);
            sum0 += s[j][0] + s[j][1];
            sum1 += s[j][2] + s[j][3];
        }
        sum0 += __shfl_xor_sync(0xffffffffu, sum0, 1);
        sum0 += __shfl_xor_sync(0xffffffffu, sum0, 2);
        sum1 += __shfl_xor_sync(0xffffffffu, sum1, 1);
        sum1 += __shfl_xor_sync(0xffffffffu, sum1, 2);
        lr0 = lr0 * c0 + sum0;
        lr1 = lr1 * c1 + sum1;
#pragma unroll
        for (int jd = 0; jd < 8; jd++) {
            o[jd][0] *= c0; o[jd][1] *= c0;
            o[jd][2] *= c1; o[jd][3] *= c1;
        }

        // ---- O += Ph Vh (1-term) ----
#pragma unroll
        for (int kk = 0; kk < 4; kk++) {
            uint32_t ph[4];
            ph[0] = cvt2h(s[2 * kk][0],     s[2 * kk][1]);
            ph[1] = cvt2h(s[2 * kk][2],     s[2 * kk][3]);
            ph[2] = cvt2h(s[2 * kk + 1][0], s[2 * kk + 1][1]);
            ph[3] = cvt2h(s[2 * kk + 1][2], s[2 * kk + 1][3]);
            const uint32_t k0 = kk * 16;
#pragma unroll
            for (int jdp = 0; jdp < 4; jdp++) {
                const uint32_t rv = k0 + rowV;
                const uint32_t uv = jdp * 2 + uV;
                const uint32_t voff = rv * 128 + ((uv ^ (rv & 7)) << 4);
                uint32_t bh4[4];
                LDSM4T(bh4, oVh + voff);
                MMA16816(o[2 * jdp],     ph, bh4);
                MMA16816(o[2 * jdp + 1], ph, bh4 + 2);
            }
        }
        __syncthreads();
    }

    // ---- epilogue: normalize, split fp16 hi/lo for the out-projection ----
    const float inv0 = 1.0f / lr0;
    const float inv1 = 1.0f / lr1;
    const int r0g = qt * 128 + q0 + (lane >> 2);
    const int cbe = (lane & 3) * 2;
#pragma unroll
    for (int jd = 0; jd < 8; jd++) {
        const int cn = colh + jd * 8 + cbe;
        uint32_t l0v, l1v;
        uint32_t h0v = split2h(o[jd][0] * inv0, o[jd][1] * inv0, l0v);
        uint32_t h1v = split2h(o[jd][2] * inv1, o[jd][3] * inv1, l1v);
        size_t i0 = base + (size_t)r0g * EMBED + cn;
        size_t i1 = base + (size_t)(r0g + 8) * EMBED + cn;
        *(uint32_t*)(Ohi + i0) = h0v;
        *(uint32_t*)(Olo + i0) = l0v;
        *(uint32_t*)(Ohi + i1) = h1v;
        *(uint32_t*)(Olo + i1) = l1v;
    }
}

// ---------------------------------------------------------------------------
// Launch
// ---------------------------------------------------------------------------
extern "C" void kernel_launch(void* const* d_in, const int* in_sizes, int n_in,
                              void* d_out, int out_size)
{
    const float* query = (const float*)d_in[0];
    const float* key   = (const float*)d_in[1];
    const float* value = (const float*)d_in[2];
    const int*   mask  = (const int*)  d_in[3];
    const float* Wq    = (const float*)d_in[4];
    const float* bq    = (const float*)d_in[5];
    const float* Wk    = (const float*)d_in[6];
    const float* bk    = (const float*)d_in[7];
    const float* Wv    = (const float*)d_in[8];
    const float* bv    = (const float*)d_in[9];
    const float* Wo    = (const float*)d_in[10];
    const float* bo    = (const float*)d_in[11];
    float* out = (float*)d_out;

    __half *ih, *wh, *qh, *kh, *vh, *aoh, *aol;
    cudaGetSymbolAddress((void**)&ih,  g_in_h);
    cudaGetSymbolAddress((void**)&wh,  g_w_h);
    cudaGetSymbolAddress((void**)&qh,  g_qh);
    cudaGetSymbolAddress((void**)&kh,  g_kh);
    cudaGetSymbolAddress((void**)&vh,  g_vh);
    cudaGetSymbolAddress((void**)&aoh, g_ao_hi);
    cudaGetSymbolAddress((void**)&aol, g_ao_lo);

    cudaFuncSetAttribute(gemm_f16x1_kernel,
                         cudaFuncAttributeMaxDynamicSharedMemorySize, GEMM1_SMEM);
    cudaFuncSetAttribute(gemm_f16x2_kernel,
                         cudaFuncAttributeMaxDynamicSharedMemorySize, GEMM2_SMEM);
    cudaFuncSetAttribute(attention_tc_kernel,
                         cudaFuncAttributeMaxDynamicSharedMemorySize, ATT_SMEM);

    // One fused convert pass: inputs + weights -> fp16 hi planes
    const int NI = TOKENS * EMBED / 4;
    const int NW = EMBED * EMBED / 4;
    cvt_all_kernel<<<(3 * NI + 4 * NW) / 256, 256>>>(
        (const float4*)query, (const float4*)key, (const float4*)value,
        (const float4*)Wq, (const float4*)Wk, (const float4*)Wv, (const float4*)Wo,
        (uint2*)ih, (uint2*)wh);

    // QKV projections: 1-term fp16 GEMM -> fp16 planes
    gemm_f16x1_kernel<<<dim3(EMBED / 128, TOKENS / 128, 3), 256, GEMM1_SMEM>>>(
        ih, TOKENS * EMBED, wh, EMBED * EMBED,
        bq, bk, bv, qh, kh, vh);

    // fp16 flash attention -> hi/lo output planes
    attention_tc_kernel<<<dim3(SEQ / 128, HEADS, BATCH), 256, ATT_SMEM>>>(
        qh, kh, vh, mask, aoh, aol);

    // Output projection: 2-term fp16 GEMM -> fp32
    gemm_f16x2_kernel<<<dim3(EMBED / 128, TOKENS / 128, 1), 256, GEMM2_SMEM>>>(
        aoh, aol, wh + (size_t)3 * EMBED * EMBED, bo, out);
}